// round 1
// baseline (speedup 1.0000x reference)
#include <cuda_runtime.h>
#include <math.h>

// Problem constants
#define T_TOK 4096
#define HIDN  2048
#define NH    8
#define NKV   4
#define HD    256
#define SWIN  1024

// Attention tiling
#define BQ   64
#define BK   64
#define QSTR 68   // padded stride for d-major Q/K smem tiles (16B-aligned, low conflict)

// Scratch (static device globals — allocation-free)
__device__ float g_q[T_TOK * HIDN];
__device__ float g_k[T_TOK * NKV * HD];
__device__ float g_v[T_TOK * NKV * HD];
__device__ float g_attn[T_TOK * HIDN];

// ---------------------------------------------------------------------------
// NT SGEMM: C[M][N] = A[M][K] * B[N][K]^T, all row-major, K contiguous.
// 128x128 block tile, 8x8 per thread (split 4+64 pattern), K-step 8,
// double-buffered smem + register prefetch. M,N % 128 == 0, K % 8 == 0.
// ---------------------------------------------------------------------------
__global__ __launch_bounds__(256) void sgemm_nt(
    const float* __restrict__ A, const float* __restrict__ B,
    float* __restrict__ C, int M, int N, int K)
{
    __shared__ float As[2][8][128];
    __shared__ float Bs[2][8][128];

    const int tid = threadIdx.x;
    const int tx = tid & 15, ty = tid >> 4;
    const int bm = blockIdx.y << 7, bn = blockIdx.x << 7;
    const int lrow = tid >> 1;            // 0..127
    const int lcol = (tid & 1) << 2;      // 0 or 4

    const float* Ag = A + (size_t)(bm + lrow) * K + lcol;
    const float* Bg = B + (size_t)(bn + lrow) * K + lcol;

    float acc[8][8];
#pragma unroll
    for (int i = 0; i < 8; i++)
#pragma unroll
        for (int j = 0; j < 8; j++) acc[i][j] = 0.f;

    float4 a4 = *(const float4*)Ag;
    float4 b4 = *(const float4*)Bg;
    As[0][lcol+0][lrow] = a4.x; As[0][lcol+1][lrow] = a4.y;
    As[0][lcol+2][lrow] = a4.z; As[0][lcol+3][lrow] = a4.w;
    Bs[0][lcol+0][lrow] = b4.x; Bs[0][lcol+1][lrow] = b4.y;
    Bs[0][lcol+2][lrow] = b4.z; Bs[0][lcol+3][lrow] = b4.w;
    __syncthreads();

    int buf = 0;
    for (int k0 = 8; k0 <= K; k0 += 8) {
        if (k0 < K) {
            a4 = *(const float4*)(Ag + k0);
            b4 = *(const float4*)(Bg + k0);
        }
#pragma unroll
        for (int kk = 0; kk < 8; kk++) {
            float4 a0 = *(const float4*)&As[buf][kk][ty * 4];
            float4 a1 = *(const float4*)&As[buf][kk][ty * 4 + 64];
            float4 b0 = *(const float4*)&Bs[buf][kk][tx * 4];
            float4 b1 = *(const float4*)&Bs[buf][kk][tx * 4 + 64];
            float av[8] = {a0.x, a0.y, a0.z, a0.w, a1.x, a1.y, a1.z, a1.w};
            float bv[8] = {b0.x, b0.y, b0.z, b0.w, b1.x, b1.y, b1.z, b1.w};
#pragma unroll
            for (int i = 0; i < 8; i++)
#pragma unroll
                for (int j = 0; j < 8; j++)
                    acc[i][j] = fmaf(av[i], bv[j], acc[i][j]);
        }
        if (k0 < K) {
            buf ^= 1;
            As[buf][lcol+0][lrow] = a4.x; As[buf][lcol+1][lrow] = a4.y;
            As[buf][lcol+2][lrow] = a4.z; As[buf][lcol+3][lrow] = a4.w;
            Bs[buf][lcol+0][lrow] = b4.x; Bs[buf][lcol+1][lrow] = b4.y;
            Bs[buf][lcol+2][lrow] = b4.z; Bs[buf][lcol+3][lrow] = b4.w;
            __syncthreads();
        }
    }

#pragma unroll
    for (int i = 0; i < 8; i++) {
        int r = bm + ty * 4 + (i & 3) + ((i >> 2) << 6);
        float4 s0 = make_float4(acc[i][0], acc[i][1], acc[i][2], acc[i][3]);
        float4 s1 = make_float4(acc[i][4], acc[i][5], acc[i][6], acc[i][7]);
        *(float4*)&C[(size_t)r * N + bn + tx * 4]      = s0;
        *(float4*)&C[(size_t)r * N + bn + tx * 4 + 64] = s1;
    }
}

// ---------------------------------------------------------------------------
// Fused per-(token, head) RMSNorm (+weight) and RoPE.
// role 0..7: q heads (q_norm_w + rope), 8..11: k heads (k_norm_w + rope),
// 12..15: v heads (norm only, no weight).
// ---------------------------------------------------------------------------
__global__ __launch_bounds__(256) void norm_rope_kernel(
    const float* __restrict__ cosv, const float* __restrict__ sinv,
    const float* __restrict__ q_nw, const float* __restrict__ k_nw)
{
    const int t = blockIdx.x;
    const int role = blockIdx.y;
    const int d = threadIdx.x;

    float* ptr;
    const float* w = nullptr;
    bool rope = true;
    if (role < 8)       { ptr = g_q + t * HIDN + role * HD; w = q_nw; }
    else if (role < 12) { ptr = g_k + t * (NKV * HD) + (role - 8) * HD; w = k_nw; }
    else                { ptr = g_v + t * (NKV * HD) + (role - 12) * HD; rope = false; }

    float x = ptr[d];
    float ss = x * x;
#pragma unroll
    for (int o = 16; o >= 1; o >>= 1) ss += __shfl_xor_sync(0xffffffffu, ss, o);

    __shared__ float red[8];
    __shared__ float ybuf[256];
    if ((d & 31) == 0) red[d >> 5] = ss;
    __syncthreads();
    float tot = 0.f;
#pragma unroll
    for (int i = 0; i < 8; i++) tot += red[i];

    float rn = rsqrtf(tot * (1.f / HD) + 1e-6f);
    float y = x * rn;
    if (w) y *= w[d];

    float out = y;
    if (rope) {
        ybuf[d] = y;
        __syncthreads();
        float c = cosv[t * HD + d];
        float s = sinv[t * HD + d];
        float rot = (d < 128) ? -ybuf[d + 128] : ybuf[d - 128];
        out = y * c + rot * s;
    }
    ptr[d] = out;
}

// ---------------------------------------------------------------------------
// Sliding-window causal flash attention (fp32, no 1/sqrt(D) scale — matches ref).
// Grid: (T/BQ, NH). Block: 256 threads (16x16). Per thread: 4 S-rows x 4 S-cols,
// O accumulator 4 rows x 16 dims. Q/K stored d-major (transposed) in smem.
// ---------------------------------------------------------------------------
__global__ __launch_bounds__(256) void attn_kernel(float* __restrict__ O)
{
    extern __shared__ float sm[];
    float* Qs = sm;                       // [HD][QSTR]
    float* Ks = Qs + HD * QSTR;           // [HD][QSTR]
    float* Vs = Ks + HD * QSTR;           // [BK][HD]
    float* Ps = Vs + BK * HD;             // [BQ][BK]

    const int qb = blockIdx.x, h = blockIdx.y;
    const int q0 = qb * BQ;
    const int kvh = h >> 1;               // GQA rep=2
    const int tid = threadIdx.x;
    const int tx = tid & 15, ty = tid >> 4;

    // Load Q tile, transposed to d-major
    const float* Qg = g_q + (size_t)q0 * HIDN + h * HD;
    for (int it = 0; it < BQ * HD / 256; ++it) {
        int idx = tid + it * 256;
        int r = idx >> 8, d = idx & 255;
        Qs[d * QSTR + r] = Qg[(size_t)r * HIDN + d];
    }

    float m_run[4], l_run[4], o_acc[4][16];
#pragma unroll
    for (int i = 0; i < 4; i++) {
        m_run[i] = -1e30f; l_run[i] = 0.f;
#pragma unroll
        for (int c = 0; c < 16; c++) o_acc[i][c] = 0.f;
    }

    int jmin = q0 - (SWIN - 1); if (jmin < 0) jmin = 0;
    const int t0 = jmin / BK;
    const int t1 = (q0 + BQ - 1) / BK;
    __syncthreads();

    for (int kt = t0; kt <= t1; ++kt) {
        const int k0 = kt * BK;
        const float* Kg = g_k + (size_t)k0 * (NKV * HD) + kvh * HD;
        const float* Vg = g_v + (size_t)k0 * (NKV * HD) + kvh * HD;
        // K tile transposed to d-major
        for (int it = 0; it < BK * HD / 256; ++it) {
            int idx = tid + it * 256;
            int r = idx >> 8, d = idx & 255;
            Ks[d * QSTR + r] = Kg[(size_t)r * (NKV * HD) + d];
        }
        // V tile natural layout, float4
        for (int it = 0; it < BK * HD / (256 * 4); ++it) {
            int idx = (tid + it * 256) * 4;
            int r = idx >> 8, d = idx & 255;
            *(float4*)&Vs[r * HD + d] = *(const float4*)&Vg[(size_t)r * (NKV * HD) + d];
        }
        __syncthreads();

        // S = Q K^T  (4x4 per thread, reduce over HD)
        float s[4][4];
#pragma unroll
        for (int i = 0; i < 4; i++)
#pragma unroll
            for (int j = 0; j < 4; j++) s[i][j] = 0.f;

#pragma unroll 4
        for (int d = 0; d < HD; d++) {
            float4 a = *(const float4*)&Qs[d * QSTR + ty * 4];
            float4 b = *(const float4*)&Ks[d * QSTR + tx * 4];
            float av[4] = {a.x, a.y, a.z, a.w};
            float bv[4] = {b.x, b.y, b.z, b.w};
#pragma unroll
            for (int i = 0; i < 4; i++)
#pragma unroll
                for (int j = 0; j < 4; j++)
                    s[i][j] = fmaf(av[i], bv[j], s[i][j]);
        }

        // Mask + online softmax (rows shared by 16-lane shuffle groups)
#pragma unroll
        for (int i = 0; i < 4; i++) {
            const int gi = q0 + ty * 4 + i;
            float mt = -1e30f;
#pragma unroll
            for (int j = 0; j < 4; j++) {
                int gj = k0 + tx * 4 + j;
                bool ok = (gj <= gi) && (gi - gj < SWIN);
                if (!ok) s[i][j] = -1e30f;
                mt = fmaxf(mt, s[i][j]);
            }
#pragma unroll
            for (int o = 8; o >= 1; o >>= 1)
                mt = fmaxf(mt, __shfl_xor_sync(0xffffffffu, mt, o));
            float mnew = fmaxf(m_run[i], mt);
            float scl = __expf(m_run[i] - mnew);
            float rs = 0.f;
#pragma unroll
            for (int j = 0; j < 4; j++) {
                float p = (s[i][j] > -1e29f) ? __expf(s[i][j] - mnew) : 0.f;
                s[i][j] = p; rs += p;
            }
#pragma unroll
            for (int o = 8; o >= 1; o >>= 1)
                rs += __shfl_xor_sync(0xffffffffu, rs, o);
            l_run[i] = l_run[i] * scl + rs;
            m_run[i] = mnew;
#pragma unroll
            for (int c = 0; c < 16; c++) o_acc[i][c] *= scl;
            *(float4*)&Ps[(ty * 4 + i) * BK + tx * 4] =
                make_float4(s[i][0], s[i][1], s[i][2], s[i][3]);
        }
        __syncthreads();

        // O += P V   (each thread: 4 rows x 16 dims)
#pragma unroll 2
        for (int j = 0; j < BK; j++) {
            float p0 = Ps[(ty * 4 + 0) * BK + j];
            float p1 = Ps[(ty * 4 + 1) * BK + j];
            float p2 = Ps[(ty * 4 + 2) * BK + j];
            float p3 = Ps[(ty * 4 + 3) * BK + j];
#pragma unroll
            for (int cb = 0; cb < 4; cb++) {
                float4 v = *(const float4*)&Vs[j * HD + tx * 4 + cb * 64];
                o_acc[0][cb*4+0] = fmaf(p0, v.x, o_acc[0][cb*4+0]);
                o_acc[0][cb*4+1] = fmaf(p0, v.y, o_acc[0][cb*4+1]);
                o_acc[0][cb*4+2] = fmaf(p0, v.z, o_acc[0][cb*4+2]);
                o_acc[0][cb*4+3] = fmaf(p0, v.w, o_acc[0][cb*4+3]);
                o_acc[1][cb*4+0] = fmaf(p1, v.x, o_acc[1][cb*4+0]);
                o_acc[1][cb*4+1] = fmaf(p1, v.y, o_acc[1][cb*4+1]);
                o_acc[1][cb*4+2] = fmaf(p1, v.z, o_acc[1][cb*4+2]);
                o_acc[1][cb*4+3] = fmaf(p1, v.w, o_acc[1][cb*4+3]);
                o_acc[2][cb*4+0] = fmaf(p2, v.x, o_acc[2][cb*4+0]);
                o_acc[2][cb*4+1] = fmaf(p2, v.y, o_acc[2][cb*4+1]);
                o_acc[2][cb*4+2] = fmaf(p2, v.z, o_acc[2][cb*4+2]);
                o_acc[2][cb*4+3] = fmaf(p2, v.w, o_acc[2][cb*4+3]);
                o_acc[3][cb*4+0] = fmaf(p3, v.x, o_acc[3][cb*4+0]);
                o_acc[3][cb*4+1] = fmaf(p3, v.y, o_acc[3][cb*4+1]);
                o_acc[3][cb*4+2] = fmaf(p3, v.z, o_acc[3][cb*4+2]);
                o_acc[3][cb*4+3] = fmaf(p3, v.w, o_acc[3][cb*4+3]);
            }
        }
        __syncthreads();
    }

    // Epilogue: O / l  -> g_attn[t][h*HD + d]
#pragma unroll
    for (int i = 0; i < 4; i++) {
        float inv = 1.f / l_run[i];
        int gi = q0 + ty * 4 + i;
#pragma unroll
        for (int cb = 0; cb < 4; cb++) {
            float4 o4 = make_float4(o_acc[i][cb*4+0] * inv, o_acc[i][cb*4+1] * inv,
                                    o_acc[i][cb*4+2] * inv, o_acc[i][cb*4+3] * inv);
            *(float4*)&O[(size_t)gi * HIDN + h * HD + tx * 4 + cb * 64] = o4;
        }
    }
}

// ---------------------------------------------------------------------------
extern "C" void kernel_launch(void* const* d_in, const int* in_sizes, int n_in,
                              void* d_out, int out_size)
{
    const float* hidden = (const float*)d_in[0];
    const float* cosv   = (const float*)d_in[1];
    const float* sinv   = (const float*)d_in[2];
    const float* q_w    = (const float*)d_in[3];
    const float* k_w    = (const float*)d_in[4];
    const float* v_w    = (const float*)d_in[5];
    const float* o_w    = (const float*)d_in[6];
    const float* q_nw   = (const float*)d_in[7];
    const float* k_nw   = (const float*)d_in[8];

    float *qp, *kp, *vp, *ap;
    cudaGetSymbolAddress((void**)&qp, g_q);
    cudaGetSymbolAddress((void**)&kp, g_k);
    cudaGetSymbolAddress((void**)&vp, g_v);
    cudaGetSymbolAddress((void**)&ap, g_attn);

    const int attn_smem = (HD * QSTR * 2 + BK * HD + BQ * BK) * (int)sizeof(float);
    cudaFuncSetAttribute(attn_kernel, cudaFuncAttributeMaxDynamicSharedMemorySize,
                         attn_smem);

    // QKV projections
    sgemm_nt<<<dim3(HIDN / 128, T_TOK / 128), 256>>>(hidden, q_w, qp, T_TOK, HIDN, HIDN);
    sgemm_nt<<<dim3(NKV * HD / 128, T_TOK / 128), 256>>>(hidden, k_w, kp, T_TOK, NKV * HD, HIDN);
    sgemm_nt<<<dim3(NKV * HD / 128, T_TOK / 128), 256>>>(hidden, v_w, vp, T_TOK, NKV * HD, HIDN);
    // RMSNorm + RoPE (q, k) and RMSNorm (v)
    norm_rope_kernel<<<dim3(T_TOK, 16), 256>>>(cosv, sinv, q_nw, k_nw);
    // Sliding-window attention
    attn_kernel<<<dim3(T_TOK / BQ, NH), 256, attn_smem>>>(ap);
    // Output projection -> d_out
    sgemm_nt<<<dim3(HIDN / 128, T_TOK / 128), 256>>>(ap, o_w, (float*)d_out, T_TOK, HIDN, HIDN);
}

// round 3
// speedup vs baseline: 1.5050x; 1.5050x over previous
#include <cuda_runtime.h>
#include <cuda_bf16.h>
#include <stdint.h>
#include <math.h>

// Problem constants
#define T_TOK 4096
#define HIDN  2048
#define NH    8
#define NKV   4
#define HD    256
#define SWIN  1024

// Attention tiling
#define BQ   64
#define BK   64
#define QSTR 68

// GEMM tiling
#define GBM 128
#define GBN 128
#define GBK 32
#define GSTAGES 3
#define GSTRIDE 40            // bf16 elems per smem row (80B, conflict-free LDSM)
#define GSTG (128 * GSTRIDE)  // elems per matrix per stage

// Scratch (static device globals — allocation-free)
__device__ float g_q[T_TOK * HIDN];
__device__ float g_k[T_TOK * NKV * HD];
__device__ float g_v[T_TOK * NKV * HD];
__device__ float g_attn[T_TOK * HIDN];

__device__ __nv_bfloat16 sb_hid_hi[T_TOK * HIDN], sb_hid_lo[T_TOK * HIDN];
__device__ __nv_bfloat16 sb_qw_hi[HIDN * HIDN],   sb_qw_lo[HIDN * HIDN];
__device__ __nv_bfloat16 sb_kw_hi[NKV * HD * HIDN], sb_kw_lo[NKV * HD * HIDN];
__device__ __nv_bfloat16 sb_vw_hi[NKV * HD * HIDN], sb_vw_lo[NKV * HD * HIDN];
__device__ __nv_bfloat16 sb_ow_hi[HIDN * HIDN],   sb_ow_lo[HIDN * HIDN];
__device__ __nv_bfloat16 sb_at_hi[T_TOK * HIDN],  sb_at_lo[T_TOK * HIDN];

// ---------------------------------------------------------------------------
// Split fp32 -> bf16 hi + bf16 lo (residual).
// ---------------------------------------------------------------------------
__global__ __launch_bounds__(256) void split_kernel(
    const float4* __restrict__ x, __nv_bfloat162* __restrict__ hi,
    __nv_bfloat162* __restrict__ lo, int n4)
{
    int i = blockIdx.x * blockDim.x + threadIdx.x;
    if (i >= n4) return;
    float4 v = x[i];
    __nv_bfloat16 h0 = __float2bfloat16_rn(v.x);
    __nv_bfloat16 h1 = __float2bfloat16_rn(v.y);
    __nv_bfloat16 h2 = __float2bfloat16_rn(v.z);
    __nv_bfloat16 h3 = __float2bfloat16_rn(v.w);
    __nv_bfloat16 l0 = __float2bfloat16_rn(v.x - __bfloat162float(h0));
    __nv_bfloat16 l1 = __float2bfloat16_rn(v.y - __bfloat162float(h1));
    __nv_bfloat16 l2 = __float2bfloat16_rn(v.z - __bfloat162float(h2));
    __nv_bfloat16 l3 = __float2bfloat16_rn(v.w - __bfloat162float(h3));
    hi[2 * i]     = __halves2bfloat162(h0, h1);
    hi[2 * i + 1] = __halves2bfloat162(h2, h3);
    lo[2 * i]     = __halves2bfloat162(l0, l1);
    lo[2 * i + 1] = __halves2bfloat162(l2, l3);
}

// ---------------------------------------------------------------------------
// Split-bf16 tensor-core NT GEMM: C[M][N] = A[M][K] * B[N][K]^T (fp32 accum).
// C ≈ Ah*Bh + Ah*Bl + Al*Bh (lo*lo dropped; ~2^-18 relative error).
// 128x128x32 tile, 8 warps (4Mx2N), warp tile 32x64, cp.async 3-stage pipeline.
// ---------------------------------------------------------------------------
#define LDSM4(R, addr) \
    asm volatile("ldmatrix.sync.aligned.m8n8.x4.shared.b16 {%0,%1,%2,%3}, [%4];" \
                 : "=r"((R)[0]), "=r"((R)[1]), "=r"((R)[2]), "=r"((R)[3]) : "r"(addr))

#define MMA16816(Cacc, A, b0, b1) \
    asm volatile("mma.sync.aligned.m16n8k16.row.col.f32.bf16.bf16.f32 " \
                 "{%0,%1,%2,%3}, {%4,%5,%6,%7}, {%8,%9}, {%0,%1,%2,%3};" \
                 : "+f"((Cacc)[0]), "+f"((Cacc)[1]), "+f"((Cacc)[2]), "+f"((Cacc)[3]) \
                 : "r"((A)[0]), "r"((A)[1]), "r"((A)[2]), "r"((A)[3]), "r"(b0), "r"(b1))

__device__ __forceinline__ unsigned int smem_u32(const void* p) {
    return (unsigned int)__cvta_generic_to_shared(p);
}

__global__ __launch_bounds__(256) void gemm_bf16split(
    const __nv_bfloat16* __restrict__ Ah, const __nv_bfloat16* __restrict__ Al,
    const __nv_bfloat16* __restrict__ Bh, const __nv_bfloat16* __restrict__ Bl,
    float* __restrict__ C, int M, int N, int K)
{
    extern __shared__ __nv_bfloat16 sm[];
    const int tid = threadIdx.x;
    const int bm = blockIdx.y * GBM, bn = blockIdx.x * GBN;
    const int lane = tid & 31, wid = tid >> 5;
    const int wm = wid & 3, wn = wid >> 2;

    // --- load issue: 16B cp.async chunks; per matrix 512 chunks, thread does 2
#define GEMM_ISSUE(buf, k0)                                                        \
    {                                                                              \
        __nv_bfloat16* base = sm + (buf) * 4 * GSTG;                               \
        _Pragma("unroll")                                                          \
        for (int half = 0; half < 2; ++half) {                                     \
            int c = tid + half * 256;                                              \
            int row = c >> 2, cc = c & 3;                                          \
            unsigned int sA = smem_u32(base + row * GSTRIDE + cc * 8);             \
            const __nv_bfloat16* gAh = Ah + (size_t)(bm + row) * K + (k0) + cc*8;  \
            const __nv_bfloat16* gAl = Al + (size_t)(bm + row) * K + (k0) + cc*8;  \
            const __nv_bfloat16* gBh = Bh + (size_t)(bn + row) * K + (k0) + cc*8;  \
            const __nv_bfloat16* gBl = Bl + (size_t)(bn + row) * K + (k0) + cc*8;  \
            asm volatile("cp.async.cg.shared.global [%0], [%1], 16;"               \
                         :: "r"(sA), "l"(gAh));                                    \
            asm volatile("cp.async.cg.shared.global [%0], [%1], 16;"               \
                         :: "r"(sA + GSTG * 2), "l"(gAl));                         \
            asm volatile("cp.async.cg.shared.global [%0], [%1], 16;"               \
                         :: "r"(sA + GSTG * 4), "l"(gBh));                         \
            asm volatile("cp.async.cg.shared.global [%0], [%1], 16;"               \
                         :: "r"(sA + GSTG * 6), "l"(gBl));                         \
        }                                                                          \
    }

    float acc[16][4];
#pragma unroll
    for (int t = 0; t < 16; ++t)
#pragma unroll
        for (int j = 0; j < 4; ++j) acc[t][j] = 0.f;

    // prologue: prefetch GSTAGES-1 stages
#pragma unroll
    for (int s = 0; s < GSTAGES - 1; ++s) {
        GEMM_ISSUE(s, s * GBK);
        asm volatile("cp.async.commit_group;");
    }

    const int iters = K / GBK;
    for (int it = 0; it < iters; ++it) {
        asm volatile("cp.async.wait_group 1;");
        __syncthreads();
        int kpre = (it + GSTAGES - 1) * GBK;
        if (kpre < K) {
            int buf = (it + GSTAGES - 1) % GSTAGES;
            GEMM_ISSUE(buf, kpre);
        }
        asm volatile("cp.async.commit_group;");

        const __nv_bfloat16* st = sm + (it % GSTAGES) * 4 * GSTG;
#pragma unroll
        for (int ks = 0; ks < 2; ++ks) {
            unsigned int afr[2][2][4];  // [mt][hi/lo][4]
#pragma unroll
            for (int mt = 0; mt < 2; ++mt) {
                int row = wm * 32 + mt * 16 + (lane & 15);
                int col = ks * 16 + (lane >> 4) * 8;
                unsigned int ad = smem_u32(st + row * GSTRIDE + col);
                LDSM4(afr[mt][0], ad);
                LDSM4(afr[mt][1], ad + GSTG * 2);
            }
            unsigned int bfr[4][2][4];  // [pair][hi/lo][4]
#pragma unroll
            for (int p = 0; p < 4; ++p) {
                int r = lane & 7, g = lane >> 3;
                int nrow = wn * 64 + p * 16 + ((g >> 1) & 1) * 8 + r;
                int col = ks * 16 + (g & 1) * 8;
                unsigned int bd = smem_u32(st + 2 * GSTG + nrow * GSTRIDE + col);
                LDSM4(bfr[p][0], bd);
                LDSM4(bfr[p][1], bd + GSTG * 2);
            }
#pragma unroll
            for (int mt = 0; mt < 2; ++mt)
#pragma unroll
                for (int nt = 0; nt < 8; ++nt) {
                    int p = nt >> 1, o = (nt & 1) * 2;
                    float* cc = acc[mt * 8 + nt];
                    MMA16816(cc, afr[mt][0], bfr[p][0][o], bfr[p][0][o + 1]);
                    MMA16816(cc, afr[mt][0], bfr[p][1][o], bfr[p][1][o + 1]);
                    MMA16816(cc, afr[mt][1], bfr[p][0][o], bfr[p][0][o + 1]);
                }
        }
    }

    // epilogue
#pragma unroll
    for (int mt = 0; mt < 2; ++mt)
#pragma unroll
        for (int nt = 0; nt < 8; ++nt) {
            float* cc = acc[mt * 8 + nt];
            int r = bm + wm * 32 + mt * 16 + (lane >> 2);
            int cl = bn + wn * 64 + nt * 8 + (lane & 3) * 2;
            *(float2*)&C[(size_t)r * N + cl]       = make_float2(cc[0], cc[1]);
            *(float2*)&C[(size_t)(r + 8) * N + cl] = make_float2(cc[2], cc[3]);
        }
#undef GEMM_ISSUE
}

// ---------------------------------------------------------------------------
// Fused per-(token, head) RMSNorm (+weight) and RoPE.
// ---------------------------------------------------------------------------
__global__ __launch_bounds__(256) void norm_rope_kernel(
    const float* __restrict__ cosv, const float* __restrict__ sinv,
    const float* __restrict__ q_nw, const float* __restrict__ k_nw)
{
    const int t = blockIdx.x;
    const int role = blockIdx.y;
    const int d = threadIdx.x;

    float* ptr;
    const float* w = nullptr;
    bool rope = true;
    if (role < 8)       { ptr = g_q + t * HIDN + role * HD; w = q_nw; }
    else if (role < 12) { ptr = g_k + t * (NKV * HD) + (role - 8) * HD; w = k_nw; }
    else                { ptr = g_v + t * (NKV * HD) + (role - 12) * HD; rope = false; }

    float x = ptr[d];
    float ss = x * x;
#pragma unroll
    for (int o = 16; o >= 1; o >>= 1) ss += __shfl_xor_sync(0xffffffffu, ss, o);

    __shared__ float red[8];
    __shared__ float ybuf[256];
    if ((d & 31) == 0) red[d >> 5] = ss;
    __syncthreads();
    float tot = 0.f;
#pragma unroll
    for (int i = 0; i < 8; i++) tot += red[i];

    float rn = rsqrtf(tot * (1.f / HD) + 1e-6f);
    float y = x * rn;
    if (w) y *= w[d];

    float out = y;
    if (rope) {
        ybuf[d] = y;
        __syncthreads();
        float c = cosv[t * HD + d];
        float s = sinv[t * HD + d];
        float rot = (d < 128) ? -ybuf[d + 128] : ybuf[d - 128];
        out = y * c + rot * s;
    }
    ptr[d] = out;
}

// ---------------------------------------------------------------------------
// Sliding-window causal flash attention (fp32, no 1/sqrt(D) scale).
// ---------------------------------------------------------------------------
__global__ __launch_bounds__(256) void attn_kernel(float* __restrict__ O)
{
    extern __shared__ float smf[];
    float* Qs = smf;
    float* Ks = Qs + HD * QSTR;
    float* Vs = Ks + HD * QSTR;
    float* Ps = Vs + BK * HD;

    const int qb = blockIdx.x, h = blockIdx.y;
    const int q0 = qb * BQ;
    const int kvh = h >> 1;
    const int tid = threadIdx.x;
    const int tx = tid & 15, ty = tid >> 4;

    const float* Qg = g_q + (size_t)q0 * HIDN + h * HD;
    for (int it = 0; it < BQ * HD / 256; ++it) {
        int idx = tid + it * 256;
        int r = idx >> 8, d = idx & 255;
        Qs[d * QSTR + r] = Qg[(size_t)r * HIDN + d];
    }

    float m_run[4], l_run[4], o_acc[4][16];
#pragma unroll
    for (int i = 0; i < 4; i++) {
        m_run[i] = -1e30f; l_run[i] = 0.f;
#pragma unroll
        for (int c = 0; c < 16; c++) o_acc[i][c] = 0.f;
    }

    int jmin = q0 - (SWIN - 1); if (jmin < 0) jmin = 0;
    const int t0 = jmin / BK;
    const int t1 = (q0 + BQ - 1) / BK;
    __syncthreads();

    for (int kt = t0; kt <= t1; ++kt) {
        const int k0 = kt * BK;
        const float* Kg = g_k + (size_t)k0 * (NKV * HD) + kvh * HD;
        const float* Vg = g_v + (size_t)k0 * (NKV * HD) + kvh * HD;
        for (int it = 0; it < BK * HD / 256; ++it) {
            int idx = tid + it * 256;
            int r = idx >> 8, d = idx & 255;
            Ks[d * QSTR + r] = Kg[(size_t)r * (NKV * HD) + d];
        }
        for (int it = 0; it < BK * HD / (256 * 4); ++it) {
            int idx = (tid + it * 256) * 4;
            int r = idx >> 8, d = idx & 255;
            *(float4*)&Vs[r * HD + d] = *(const float4*)&Vg[(size_t)r * (NKV * HD) + d];
        }
        __syncthreads();

        float s[4][4];
#pragma unroll
        for (int i = 0; i < 4; i++)
#pragma unroll
            for (int j = 0; j < 4; j++) s[i][j] = 0.f;

#pragma unroll 4
        for (int d = 0; d < HD; d++) {
            float4 a = *(const float4*)&Qs[d * QSTR + ty * 4];
            float4 b = *(const float4*)&Ks[d * QSTR + tx * 4];
            float av[4] = {a.x, a.y, a.z, a.w};
            float bv[4] = {b.x, b.y, b.z, b.w};
#pragma unroll
            for (int i = 0; i < 4; i++)
#pragma unroll
                for (int j = 0; j < 4; j++)
                    s[i][j] = fmaf(av[i], bv[j], s[i][j]);
        }

#pragma unroll
        for (int i = 0; i < 4; i++) {
            const int gi = q0 + ty * 4 + i;
            float mt = -1e30f;
#pragma unroll
            for (int j = 0; j < 4; j++) {
                int gj = k0 + tx * 4 + j;
                bool ok = (gj <= gi) && (gi - gj < SWIN);
                if (!ok) s[i][j] = -1e30f;
                mt = fmaxf(mt, s[i][j]);
            }
#pragma unroll
            for (int o = 8; o >= 1; o >>= 1)
                mt = fmaxf(mt, __shfl_xor_sync(0xffffffffu, mt, o));
            float mnew = fmaxf(m_run[i], mt);
            float scl = __expf(m_run[i] - mnew);
            float rs = 0.f;
#pragma unroll
            for (int j = 0; j < 4; j++) {
                float p = (s[i][j] > -1e29f) ? __expf(s[i][j] - mnew) : 0.f;
                s[i][j] = p; rs += p;
            }
#pragma unroll
            for (int o = 8; o >= 1; o >>= 1)
                rs += __shfl_xor_sync(0xffffffffu, rs, o);
            l_run[i] = l_run[i] * scl + rs;
            m_run[i] = mnew;
#pragma unroll
            for (int c = 0; c < 16; c++) o_acc[i][c] *= scl;
            *(float4*)&Ps[(ty * 4 + i) * BK + tx * 4] =
                make_float4(s[i][0], s[i][1], s[i][2], s[i][3]);
        }
        __syncthreads();

#pragma unroll 2
        for (int j = 0; j < BK; j++) {
            float p0 = Ps[(ty * 4 + 0) * BK + j];
            float p1 = Ps[(ty * 4 + 1) * BK + j];
            float p2 = Ps[(ty * 4 + 2) * BK + j];
            float p3 = Ps[(ty * 4 + 3) * BK + j];
#pragma unroll
            for (int cb = 0; cb < 4; cb++) {
                float4 v = *(const float4*)&Vs[j * HD + tx * 4 + cb * 64];
                o_acc[0][cb*4+0] = fmaf(p0, v.x, o_acc[0][cb*4+0]);
                o_acc[0][cb*4+1] = fmaf(p0, v.y, o_acc[0][cb*4+1]);
                o_acc[0][cb*4+2] = fmaf(p0, v.z, o_acc[0][cb*4+2]);
                o_acc[0][cb*4+3] = fmaf(p0, v.w, o_acc[0][cb*4+3]);
                o_acc[1][cb*4+0] = fmaf(p1, v.x, o_acc[1][cb*4+0]);
                o_acc[1][cb*4+1] = fmaf(p1, v.y, o_acc[1][cb*4+1]);
                o_acc[1][cb*4+2] = fmaf(p1, v.z, o_acc[1][cb*4+2]);
                o_acc[1][cb*4+3] = fmaf(p1, v.w, o_acc[1][cb*4+3]);
                o_acc[2][cb*4+0] = fmaf(p2, v.x, o_acc[2][cb*4+0]);
                o_acc[2][cb*4+1] = fmaf(p2, v.y, o_acc[2][cb*4+1]);
                o_acc[2][cb*4+2] = fmaf(p2, v.z, o_acc[2][cb*4+2]);
                o_acc[2][cb*4+3] = fmaf(p2, v.w, o_acc[2][cb*4+3]);
                o_acc[3][cb*4+0] = fmaf(p3, v.x, o_acc[3][cb*4+0]);
                o_acc[3][cb*4+1] = fmaf(p3, v.y, o_acc[3][cb*4+1]);
                o_acc[3][cb*4+2] = fmaf(p3, v.z, o_acc[3][cb*4+2]);
                o_acc[3][cb*4+3] = fmaf(p3, v.w, o_acc[3][cb*4+3]);
            }
        }
        __syncthreads();
    }

#pragma unroll
    for (int i = 0; i < 4; i++) {
        float inv = 1.f / l_run[i];
        int gi = q0 + ty * 4 + i;
#pragma unroll
        for (int cb = 0; cb < 4; cb++) {
            float4 o4 = make_float4(o_acc[i][cb*4+0] * inv, o_acc[i][cb*4+1] * inv,
                                    o_acc[i][cb*4+2] * inv, o_acc[i][cb*4+3] * inv);
            *(float4*)&O[(size_t)gi * HIDN + h * HD + tx * 4 + cb * 64] = o4;
        }
    }
}

// ---------------------------------------------------------------------------
extern "C" void kernel_launch(void* const* d_in, const int* in_sizes, int n_in,
                              void* d_out, int out_size)
{
    const float* hidden = (const float*)d_in[0];
    const float* cosv   = (const float*)d_in[1];
    const float* sinv   = (const float*)d_in[2];
    const float* q_w    = (const float*)d_in[3];
    const float* k_w    = (const float*)d_in[4];
    const float* v_w    = (const float*)d_in[5];
    const float* o_w    = (const float*)d_in[6];
    const float* q_nw   = (const float*)d_in[7];
    const float* k_nw   = (const float*)d_in[8];

    float *qp, *kp, *vp, *ap;
    cudaGetSymbolAddress((void**)&qp, g_q);
    cudaGetSymbolAddress((void**)&kp, g_k);
    cudaGetSymbolAddress((void**)&vp, g_v);
    cudaGetSymbolAddress((void**)&ap, g_attn);

    __nv_bfloat16 *hid_h, *hid_l, *qw_h, *qw_l, *kw_h, *kw_l, *vw_h, *vw_l,
                  *ow_h, *ow_l, *at_h, *at_l;
    cudaGetSymbolAddress((void**)&hid_h, sb_hid_hi);
    cudaGetSymbolAddress((void**)&hid_l, sb_hid_lo);
    cudaGetSymbolAddress((void**)&qw_h, sb_qw_hi);
    cudaGetSymbolAddress((void**)&qw_l, sb_qw_lo);
    cudaGetSymbolAddress((void**)&kw_h, sb_kw_hi);
    cudaGetSymbolAddress((void**)&kw_l, sb_kw_lo);
    cudaGetSymbolAddress((void**)&vw_h, sb_vw_hi);
    cudaGetSymbolAddress((void**)&vw_l, sb_vw_lo);
    cudaGetSymbolAddress((void**)&ow_h, sb_ow_hi);
    cudaGetSymbolAddress((void**)&ow_l, sb_ow_lo);
    cudaGetSymbolAddress((void**)&at_h, sb_at_hi);
    cudaGetSymbolAddress((void**)&at_l, sb_at_lo);

    const int attn_smem = (HD * QSTR * 2 + BK * HD + BQ * BK) * (int)sizeof(float);
    cudaFuncSetAttribute(attn_kernel, cudaFuncAttributeMaxDynamicSharedMemorySize,
                         attn_smem);
    const int gemm_smem = GSTAGES * 4 * GSTG * (int)sizeof(__nv_bfloat16);
    cudaFuncSetAttribute(gemm_bf16split, cudaFuncAttributeMaxDynamicSharedMemorySize,
                         gemm_smem);

    auto split = [&](const float* src, __nv_bfloat16* h, __nv_bfloat16* l, int n) {
        int n4 = n / 4;
        split_kernel<<<(n4 + 255) / 256, 256>>>(
            (const float4*)src, (__nv_bfloat162*)h, (__nv_bfloat162*)l, n4);
    };

    // Splits
    split(hidden, hid_h, hid_l, T_TOK * HIDN);
    split(q_w, qw_h, qw_l, HIDN * HIDN);
    split(k_w, kw_h, kw_l, NKV * HD * HIDN);
    split(v_w, vw_h, vw_l, NKV * HD * HIDN);
    split(o_w, ow_h, ow_l, HIDN * HIDN);

    // QKV projections (tensor cores, split-bf16)
    gemm_bf16split<<<dim3(HIDN / GBN, T_TOK / GBM), 256, gemm_smem>>>(
        hid_h, hid_l, qw_h, qw_l, qp, T_TOK, HIDN, HIDN);
    gemm_bf16split<<<dim3(NKV * HD / GBN, T_TOK / GBM), 256, gemm_smem>>>(
        hid_h, hid_l, kw_h, kw_l, kp, T_TOK, NKV * HD, HIDN);
    gemm_bf16split<<<dim3(NKV * HD / GBN, T_TOK / GBM), 256, gemm_smem>>>(
        hid_h, hid_l, vw_h, vw_l, vp, T_TOK, NKV * HD, HIDN);

    // RMSNorm + RoPE
    norm_rope_kernel<<<dim3(T_TOK, 16), 256>>>(cosv, sinv, q_nw, k_nw);
    // Sliding-window attention
    attn_kernel<<<dim3(T_TOK / BQ, NH), 256, attn_smem>>>(ap);

    // Output projection
    split(ap, at_h, at_l, T_TOK * HIDN);
    gemm_bf16split<<<dim3(HIDN / GBN, T_TOK / GBM), 256, gemm_smem>>>(
        at_h, at_l, ow_h, ow_l, (float*)d_out, T_TOK, HIDN, HIDN);
}

// round 4
// speedup vs baseline: 2.1188x; 1.4078x over previous
#include <cuda_runtime.h>
#include <cuda_bf16.h>
#include <stdint.h>
#include <math.h>

// Problem constants
#define T_TOK 4096
#define HIDN  2048
#define NH    8
#define NKV   4
#define HD    256
#define SWIN  1024

// GEMM tiling
#define GBM 128
#define GBN 128
#define GBK 32
#define GSTAGES 3
#define GSTRIDE 40
#define GSTG (128 * GSTRIDE)

// Attention smem layout (bf16 element offsets)
#define DS   264                 // Q/K/V tile row stride (bf16)
#define PSTR 72                  // P tile row stride (bf16)
#define ATT_QH 0
#define ATT_QL (64 * DS)
#define ATT_KH (2 * 64 * DS)
#define ATT_KL (3 * 64 * DS)
#define ATT_VH (4 * 64 * DS)
#define ATT_VL (5 * 64 * DS)
#define ATT_PH (6 * 64 * DS)
#define ATT_PL (ATT_PH + 64 * PSTR)
#define ATT_F  (ATT_PL + 64 * PSTR)   // float stats start (bf16 idx)
#define ATT_SMEM_BYTES (ATT_F * 2 + 448 * 4)

// Scratch (static device globals — allocation-free)
__device__ float g_q[T_TOK * HIDN];
__device__ float g_k[T_TOK * NKV * HD];
__device__ float g_v[T_TOK * NKV * HD];

__device__ __nv_bfloat16 sb_hid_hi[T_TOK * HIDN], sb_hid_lo[T_TOK * HIDN];
__device__ __nv_bfloat16 sb_qw_hi[HIDN * HIDN],   sb_qw_lo[HIDN * HIDN];
__device__ __nv_bfloat16 sb_kw_hi[NKV * HD * HIDN], sb_kw_lo[NKV * HD * HIDN];
__device__ __nv_bfloat16 sb_vw_hi[NKV * HD * HIDN], sb_vw_lo[NKV * HD * HIDN];
__device__ __nv_bfloat16 sb_ow_hi[HIDN * HIDN],   sb_ow_lo[HIDN * HIDN];
__device__ __nv_bfloat16 sb_at_hi[T_TOK * HIDN],  sb_at_lo[T_TOK * HIDN];

__device__ __nv_bfloat16 sbq_hi[T_TOK * HIDN],     sbq_lo[T_TOK * HIDN];
__device__ __nv_bfloat16 sbk_hi[T_TOK * NKV * HD], sbk_lo[T_TOK * NKV * HD];
__device__ __nv_bfloat16 sbv_hi[T_TOK * NKV * HD], sbv_lo[T_TOK * NKV * HD];

// ---------------------------------------------------------------------------
#define LDSM4(R, addr) \
    asm volatile("ldmatrix.sync.aligned.m8n8.x4.shared.b16 {%0,%1,%2,%3}, [%4];" \
                 : "=r"((R)[0]), "=r"((R)[1]), "=r"((R)[2]), "=r"((R)[3]) : "r"(addr))

#define LDSM4T(R, addr) \
    asm volatile("ldmatrix.sync.aligned.m8n8.x4.trans.shared.b16 {%0,%1,%2,%3}, [%4];" \
                 : "=r"((R)[0]), "=r"((R)[1]), "=r"((R)[2]), "=r"((R)[3]) : "r"(addr))

#define MMA16816(Cacc, A, b0, b1) \
    asm volatile("mma.sync.aligned.m16n8k16.row.col.f32.bf16.bf16.f32 " \
                 "{%0,%1,%2,%3}, {%4,%5,%6,%7}, {%8,%9}, {%0,%1,%2,%3};" \
                 : "+f"((Cacc)[0]), "+f"((Cacc)[1]), "+f"((Cacc)[2]), "+f"((Cacc)[3]) \
                 : "r"((A)[0]), "r"((A)[1]), "r"((A)[2]), "r"((A)[3]), "r"(b0), "r"(b1))

#define CPA16(dst, src) \
    asm volatile("cp.async.cg.shared.global [%0], [%1], 16;" :: "r"(dst), "l"(src))

__device__ __forceinline__ unsigned int smem_u32(const void* p) {
    return (unsigned int)__cvta_generic_to_shared(p);
}

// ---------------------------------------------------------------------------
// Split fp32 -> bf16 hi + bf16 lo (residual).
// ---------------------------------------------------------------------------
__global__ __launch_bounds__(256) void split_kernel(
    const float4* __restrict__ x, __nv_bfloat162* __restrict__ hi,
    __nv_bfloat162* __restrict__ lo, int n4)
{
    int i = blockIdx.x * blockDim.x + threadIdx.x;
    if (i >= n4) return;
    float4 v = x[i];
    __nv_bfloat16 h0 = __float2bfloat16_rn(v.x);
    __nv_bfloat16 h1 = __float2bfloat16_rn(v.y);
    __nv_bfloat16 h2 = __float2bfloat16_rn(v.z);
    __nv_bfloat16 h3 = __float2bfloat16_rn(v.w);
    __nv_bfloat16 l0 = __float2bfloat16_rn(v.x - __bfloat162float(h0));
    __nv_bfloat16 l1 = __float2bfloat16_rn(v.y - __bfloat162float(h1));
    __nv_bfloat16 l2 = __float2bfloat16_rn(v.z - __bfloat162float(h2));
    __nv_bfloat16 l3 = __float2bfloat16_rn(v.w - __bfloat162float(h3));
    hi[2 * i]     = __halves2bfloat162(h0, h1);
    hi[2 * i + 1] = __halves2bfloat162(h2, h3);
    lo[2 * i]     = __halves2bfloat162(l0, l1);
    lo[2 * i + 1] = __halves2bfloat162(l2, l3);
}

// ---------------------------------------------------------------------------
// Split-bf16 tensor-core NT GEMM (unchanged from R3 — validated).
// ---------------------------------------------------------------------------
__global__ __launch_bounds__(256) void gemm_bf16split(
    const __nv_bfloat16* __restrict__ Ah, const __nv_bfloat16* __restrict__ Al,
    const __nv_bfloat16* __restrict__ Bh, const __nv_bfloat16* __restrict__ Bl,
    float* __restrict__ C, int M, int N, int K)
{
    extern __shared__ __nv_bfloat16 sm[];
    const int tid = threadIdx.x;
    const int bm = blockIdx.y * GBM, bn = blockIdx.x * GBN;
    const int lane = tid & 31, wid = tid >> 5;
    const int wm = wid & 3, wn = wid >> 2;

#define GEMM_ISSUE(buf, k0)                                                        \
    {                                                                              \
        __nv_bfloat16* base = sm + (buf) * 4 * GSTG;                               \
        _Pragma("unroll")                                                          \
        for (int half = 0; half < 2; ++half) {                                     \
            int c = tid + half * 256;                                              \
            int row = c >> 2, cc = c & 3;                                          \
            unsigned int sA = smem_u32(base + row * GSTRIDE + cc * 8);             \
            const __nv_bfloat16* gAh = Ah + (size_t)(bm + row) * K + (k0) + cc*8;  \
            const __nv_bfloat16* gAl = Al + (size_t)(bm + row) * K + (k0) + cc*8;  \
            const __nv_bfloat16* gBh = Bh + (size_t)(bn + row) * K + (k0) + cc*8;  \
            const __nv_bfloat16* gBl = Bl + (size_t)(bn + row) * K + (k0) + cc*8;  \
            CPA16(sA, gAh);                                                        \
            CPA16(sA + GSTG * 2, gAl);                                             \
            CPA16(sA + GSTG * 4, gBh);                                             \
            CPA16(sA + GSTG * 6, gBl);                                             \
        }                                                                          \
    }

    float acc[16][4];
#pragma unroll
    for (int t = 0; t < 16; ++t)
#pragma unroll
        for (int j = 0; j < 4; ++j) acc[t][j] = 0.f;

#pragma unroll
    for (int s = 0; s < GSTAGES - 1; ++s) {
        GEMM_ISSUE(s, s * GBK);
        asm volatile("cp.async.commit_group;");
    }

    const int iters = K / GBK;
    for (int it = 0; it < iters; ++it) {
        asm volatile("cp.async.wait_group 1;");
        __syncthreads();
        int kpre = (it + GSTAGES - 1) * GBK;
        if (kpre < K) {
            int buf = (it + GSTAGES - 1) % GSTAGES;
            GEMM_ISSUE(buf, kpre);
        }
        asm volatile("cp.async.commit_group;");

        const __nv_bfloat16* st = sm + (it % GSTAGES) * 4 * GSTG;
#pragma unroll
        for (int ks = 0; ks < 2; ++ks) {
            unsigned int afr[2][2][4];
#pragma unroll
            for (int mt = 0; mt < 2; ++mt) {
                int row = wm * 32 + mt * 16 + (lane & 15);
                int col = ks * 16 + (lane >> 4) * 8;
                unsigned int ad = smem_u32(st + row * GSTRIDE + col);
                LDSM4(afr[mt][0], ad);
                LDSM4(afr[mt][1], ad + GSTG * 2);
            }
            unsigned int bfr[4][2][4];
#pragma unroll
            for (int p = 0; p < 4; ++p) {
                int r = lane & 7, g = lane >> 3;
                int nrow = wn * 64 + p * 16 + ((g >> 1) & 1) * 8 + r;
                int col = ks * 16 + (g & 1) * 8;
                unsigned int bd = smem_u32(st + 2 * GSTG + nrow * GSTRIDE + col);
                LDSM4(bfr[p][0], bd);
                LDSM4(bfr[p][1], bd + GSTG * 2);
            }
#pragma unroll
            for (int mt = 0; mt < 2; ++mt)
#pragma unroll
                for (int nt = 0; nt < 8; ++nt) {
                    int p = nt >> 1, o = (nt & 1) * 2;
                    float* cc = acc[mt * 8 + nt];
                    MMA16816(cc, afr[mt][0], bfr[p][0][o], bfr[p][0][o + 1]);
                    MMA16816(cc, afr[mt][0], bfr[p][1][o], bfr[p][1][o + 1]);
                    MMA16816(cc, afr[mt][1], bfr[p][0][o], bfr[p][0][o + 1]);
                }
        }
    }

#pragma unroll
    for (int mt = 0; mt < 2; ++mt)
#pragma unroll
        for (int nt = 0; nt < 8; ++nt) {
            float* cc = acc[mt * 8 + nt];
            int r = bm + wm * 32 + mt * 16 + (lane >> 2);
            int cl = bn + wn * 64 + nt * 8 + (lane & 3) * 2;
            *(float2*)&C[(size_t)r * N + cl]       = make_float2(cc[0], cc[1]);
            *(float2*)&C[(size_t)(r + 8) * N + cl] = make_float2(cc[2], cc[3]);
        }
#undef GEMM_ISSUE
}

// ---------------------------------------------------------------------------
// Fused per-(token, head) RMSNorm (+weight) + RoPE -> bf16 hi/lo outputs.
// ---------------------------------------------------------------------------
__global__ __launch_bounds__(256) void norm_rope_kernel(
    const float* __restrict__ cosv, const float* __restrict__ sinv,
    const float* __restrict__ q_nw, const float* __restrict__ k_nw)
{
    const int t = blockIdx.x;
    const int role = blockIdx.y;
    const int d = threadIdx.x;

    const float* src;
    __nv_bfloat16 *dh, *dl;
    const float* w = nullptr;
    bool rope = true;
    size_t off;
    if (role < 8) {
        src = g_q + (size_t)t * HIDN + role * HD; w = q_nw;
        off = (size_t)t * HIDN + role * HD + d; dh = sbq_hi; dl = sbq_lo;
    } else if (role < 12) {
        src = g_k + (size_t)t * (NKV * HD) + (role - 8) * HD; w = k_nw;
        off = (size_t)t * (NKV * HD) + (role - 8) * HD + d; dh = sbk_hi; dl = sbk_lo;
    } else {
        src = g_v + (size_t)t * (NKV * HD) + (role - 12) * HD; rope = false;
        off = (size_t)t * (NKV * HD) + (role - 12) * HD + d; dh = sbv_hi; dl = sbv_lo;
    }

    float x = src[d];
    float ss = x * x;
#pragma unroll
    for (int o = 16; o >= 1; o >>= 1) ss += __shfl_xor_sync(0xffffffffu, ss, o);

    __shared__ float red[8];
    __shared__ float ybuf[256];
    if ((d & 31) == 0) red[d >> 5] = ss;
    __syncthreads();
    float tot = 0.f;
#pragma unroll
    for (int i = 0; i < 8; i++) tot += red[i];

    float rn = rsqrtf(tot * (1.f / HD) + 1e-6f);
    float y = x * rn;
    if (w) y *= w[d];

    float out = y;
    if (rope) {
        ybuf[d] = y;
        __syncthreads();
        float c = cosv[(size_t)t * HD + d];
        float s = sinv[(size_t)t * HD + d];
        float rot = (d < 128) ? -ybuf[d + 128] : ybuf[d - 128];
        out = y * c + rot * s;
    }
    __nv_bfloat16 h = __float2bfloat16_rn(out);
    __nv_bfloat16 l = __float2bfloat16_rn(out - __bfloat162float(h));
    dh[off] = h;
    dl[off] = l;
}

// ---------------------------------------------------------------------------
// Sliding-window flash attention, split-bf16 tensor cores.
// Grid (T/64, NH), 256 threads. Phase-1: S=QK^T 4Mx2N warps; Phase-2: O+=PV
// 2Mx4N warps with V via ldmatrix.trans. Epilogue writes bf16 hi/lo directly.
// ---------------------------------------------------------------------------
__global__ __launch_bounds__(256) void attn_mma_kernel(
    const __nv_bfloat16* __restrict__ Qh, const __nv_bfloat16* __restrict__ Ql,
    const __nv_bfloat16* __restrict__ Kh, const __nv_bfloat16* __restrict__ Kl,
    const __nv_bfloat16* __restrict__ Vh, const __nv_bfloat16* __restrict__ Vl,
    __nv_bfloat16* __restrict__ Oh, __nv_bfloat16* __restrict__ Ol)
{
    extern __shared__ __nv_bfloat16 sm[];
    float* fb     = (float*)(sm + ATT_F);
    float* m_run  = fb;          // [64]
    float* l_run  = fb + 64;     // [64]
    float* rscale = fb + 128;    // [64]
    float* pmax   = fb + 192;    // [2][64]
    float* psum   = fb + 320;    // [2][64]

    const int qb = blockIdx.x, h = blockIdx.y;
    const int q0 = qb * 64;
    const int kvh = h >> 1;
    const int tid = threadIdx.x;
    const int lane = tid & 31, wid = tid >> 5;
    const int wm = wid & 3, wn = wid >> 2;    // phase-1
    const int wm2 = wid & 1, wn2 = wid >> 1;  // phase-2

    if (tid < 64) { m_run[tid] = -1e30f; l_run[tid] = 0.f; }

    // Load Q tile (hi/lo)
    for (int i = tid; i < 2048; i += 256) {
        int r = i >> 5, c = (i & 31) * 8;
        size_t g = (size_t)(q0 + r) * HIDN + h * HD + c;
        CPA16(smem_u32(sm + ATT_QH + r * DS + c), Qh + g);
        CPA16(smem_u32(sm + ATT_QL + r * DS + c), Ql + g);
    }
    asm volatile("cp.async.commit_group;");

    float o_acc[2][8][4];
#pragma unroll
    for (int mt = 0; mt < 2; ++mt)
#pragma unroll
        for (int nt = 0; nt < 8; ++nt)
#pragma unroll
            for (int e = 0; e < 4; ++e) o_acc[mt][nt][e] = 0.f;

    int jmin = q0 - (SWIN - 1); if (jmin < 0) jmin = 0;
    const int t0 = jmin >> 6;
    const int t1 = (q0 + 63) >> 6;

    for (int kt = t0; kt <= t1; ++kt) {
        const int k0 = kt * 64;
        // Load K/V tiles (hi/lo)
        for (int i = tid; i < 2048; i += 256) {
            int r = i >> 5, c = (i & 31) * 8;
            size_t g = (size_t)(k0 + r) * (NKV * HD) + kvh * HD + c;
            CPA16(smem_u32(sm + ATT_KH + r * DS + c), Kh + g);
            CPA16(smem_u32(sm + ATT_KL + r * DS + c), Kl + g);
            CPA16(smem_u32(sm + ATT_VH + r * DS + c), Vh + g);
            CPA16(smem_u32(sm + ATT_VL + r * DS + c), Vl + g);
        }
        asm volatile("cp.async.commit_group;");
        asm volatile("cp.async.wait_group 0;");
        __syncthreads();

        // ---- Phase 1: S = Q K^T (3-product split) ----
        float sacc[4][4];
#pragma unroll
        for (int nt = 0; nt < 4; ++nt)
#pragma unroll
            for (int e = 0; e < 4; ++e) sacc[nt][e] = 0.f;

#pragma unroll 4
        for (int ks = 0; ks < 16; ++ks) {
            unsigned int ah[4], al[4];
            {
                int row = wm * 16 + (lane & 15);
                int col = ks * 16 + (lane >> 4) * 8;
                LDSM4(ah, smem_u32(sm + ATT_QH + row * DS + col));
                LDSM4(al, smem_u32(sm + ATT_QL + row * DS + col));
            }
#pragma unroll
            for (int p = 0; p < 2; ++p) {
                int nrow = wn * 32 + p * 16 + ((lane >> 4) << 3) + (lane & 7);
                int col = ks * 16 + ((lane >> 3) & 1) * 8;
                unsigned int bh[4], bl[4];
                LDSM4(bh, smem_u32(sm + ATT_KH + nrow * DS + col));
                LDSM4(bl, smem_u32(sm + ATT_KL + nrow * DS + col));
#pragma unroll
                for (int o = 0; o < 4; o += 2) {
                    float* cc = sacc[p * 2 + (o >> 1)];
                    MMA16816(cc, ah, bh[o], bh[o + 1]);
                    MMA16816(cc, ah, bl[o], bl[o + 1]);
                    MMA16816(cc, al, bh[o], bh[o + 1]);
                }
            }
        }

        // Mask
        const int r_lo = q0 + wm * 16 + (lane >> 2);
        const int r_hi = r_lo + 8;
#pragma unroll
        for (int nt = 0; nt < 4; ++nt) {
#pragma unroll
            for (int e = 0; e < 2; ++e) {
                int j = k0 + wn * 32 + nt * 8 + (lane & 3) * 2 + e;
                if (!(j <= r_lo && r_lo - j < SWIN)) sacc[nt][e] = -1e30f;
                if (!(j <= r_hi && r_hi - j < SWIN)) sacc[nt][e + 2] = -1e30f;
            }
        }

        // Partial row max
        float mx0 = -1e30f, mx1 = -1e30f;
#pragma unroll
        for (int nt = 0; nt < 4; ++nt) {
            mx0 = fmaxf(mx0, fmaxf(sacc[nt][0], sacc[nt][1]));
            mx1 = fmaxf(mx1, fmaxf(sacc[nt][2], sacc[nt][3]));
        }
        mx0 = fmaxf(mx0, __shfl_xor_sync(0xffffffffu, mx0, 1));
        mx0 = fmaxf(mx0, __shfl_xor_sync(0xffffffffu, mx0, 2));
        mx1 = fmaxf(mx1, __shfl_xor_sync(0xffffffffu, mx1, 1));
        mx1 = fmaxf(mx1, __shfl_xor_sync(0xffffffffu, mx1, 2));
        if ((lane & 3) == 0) {
            pmax[wn * 64 + wm * 16 + (lane >> 2)]     = mx0;
            pmax[wn * 64 + wm * 16 + 8 + (lane >> 2)] = mx1;
        }
        __syncthreads();

        if (tid < 64) {
            float mo = m_run[tid];
            float mn = fmaxf(mo, fmaxf(pmax[tid], pmax[64 + tid]));
            rscale[tid] = __expf(mo - mn);
            m_run[tid] = mn;
        }
        __syncthreads();

        // P = exp(S - m), write bf16 hi/lo, partial row sums
        {
            float m0v = m_run[wm * 16 + (lane >> 2)];
            float m1v = m_run[wm * 16 + 8 + (lane >> 2)];
            float s0 = 0.f, s1 = 0.f;
#pragma unroll
            for (int nt = 0; nt < 4; ++nt) {
                float p00 = (sacc[nt][0] > -1e29f) ? __expf(sacc[nt][0] - m0v) : 0.f;
                float p01 = (sacc[nt][1] > -1e29f) ? __expf(sacc[nt][1] - m0v) : 0.f;
                float p10 = (sacc[nt][2] > -1e29f) ? __expf(sacc[nt][2] - m1v) : 0.f;
                float p11 = (sacc[nt][3] > -1e29f) ? __expf(sacc[nt][3] - m1v) : 0.f;
                s0 += p00 + p01; s1 += p10 + p11;
                int colb = wn * 32 + nt * 8 + (lane & 3) * 2;
                int rowL = wm * 16 + (lane >> 2);
                int rowH = rowL + 8;
                __nv_bfloat16 h00 = __float2bfloat16_rn(p00);
                __nv_bfloat16 h01 = __float2bfloat16_rn(p01);
                __nv_bfloat16 h10 = __float2bfloat16_rn(p10);
                __nv_bfloat16 h11 = __float2bfloat16_rn(p11);
                *(__nv_bfloat162*)(sm + ATT_PH + rowL * PSTR + colb) =
                    __halves2bfloat162(h00, h01);
                *(__nv_bfloat162*)(sm + ATT_PH + rowH * PSTR + colb) =
                    __halves2bfloat162(h10, h11);
                *(__nv_bfloat162*)(sm + ATT_PL + rowL * PSTR + colb) =
                    __halves2bfloat162(
                        __float2bfloat16_rn(p00 - __bfloat162float(h00)),
                        __float2bfloat16_rn(p01 - __bfloat162float(h01)));
                *(__nv_bfloat162*)(sm + ATT_PL + rowH * PSTR + colb) =
                    __halves2bfloat162(
                        __float2bfloat16_rn(p10 - __bfloat162float(h10)),
                        __float2bfloat16_rn(p11 - __bfloat162float(h11)));
            }
            s0 += __shfl_xor_sync(0xffffffffu, s0, 1);
            s0 += __shfl_xor_sync(0xffffffffu, s0, 2);
            s1 += __shfl_xor_sync(0xffffffffu, s1, 1);
            s1 += __shfl_xor_sync(0xffffffffu, s1, 2);
            if ((lane & 3) == 0) {
                psum[wn * 64 + wm * 16 + (lane >> 2)]     = s0;
                psum[wn * 64 + wm * 16 + 8 + (lane >> 2)] = s1;
            }
        }
        __syncthreads();

        if (tid < 64)
            l_run[tid] = l_run[tid] * rscale[tid] + psum[tid] + psum[64 + tid];

        // ---- Phase 2: O = O*scale + P V ----
#pragma unroll
        for (int mt = 0; mt < 2; ++mt) {
            float sL = rscale[wm2 * 32 + mt * 16 + (lane >> 2)];
            float sH = rscale[wm2 * 32 + mt * 16 + 8 + (lane >> 2)];
#pragma unroll
            for (int nt = 0; nt < 8; ++nt) {
                o_acc[mt][nt][0] *= sL; o_acc[mt][nt][1] *= sL;
                o_acc[mt][nt][2] *= sH; o_acc[mt][nt][3] *= sH;
            }
        }

#pragma unroll
        for (int ks2 = 0; ks2 < 4; ++ks2) {
            unsigned int aph[2][4], apl[2][4];
#pragma unroll
            for (int mt = 0; mt < 2; ++mt) {
                int row = wm2 * 32 + mt * 16 + (lane & 15);
                int col = ks2 * 16 + (lane >> 4) * 8;
                LDSM4(aph[mt], smem_u32(sm + ATT_PH + row * PSTR + col));
                LDSM4(apl[mt], smem_u32(sm + ATT_PL + row * PSTR + col));
            }
#pragma unroll
            for (int ng = 0; ng < 4; ++ng) {
                int vr = ks2 * 16 + ((lane >> 3) & 1) * 8 + (lane & 7);
                int vc = wn2 * 64 + ng * 16 + (lane >> 4) * 8;
                unsigned int bvh[4], bvl[4];
                LDSM4T(bvh, smem_u32(sm + ATT_VH + vr * DS + vc));
                LDSM4T(bvl, smem_u32(sm + ATT_VL + vr * DS + vc));
#pragma unroll
                for (int mt = 0; mt < 2; ++mt)
#pragma unroll
                    for (int o = 0; o < 4; o += 2) {
                        float* cc = o_acc[mt][ng * 2 + (o >> 1)];
                        MMA16816(cc, aph[mt], bvh[o], bvh[o + 1]);
                        MMA16816(cc, aph[mt], bvl[o], bvl[o + 1]);
                        MMA16816(cc, apl[mt], bvh[o], bvh[o + 1]);
                    }
            }
        }
        __syncthreads();  // protect K/V/P before next tile load
    }

    // Epilogue: divide by l, split to bf16 hi/lo, store
#pragma unroll
    for (int mt = 0; mt < 2; ++mt) {
        int rL = wm2 * 32 + mt * 16 + (lane >> 2);
        int rH = rL + 8;
        float invL = 1.f / l_run[rL];
        float invH = 1.f / l_run[rH];
#pragma unroll
        for (int nt = 0; nt < 8; ++nt) {
            int col = wn2 * 64 + nt * 8 + (lane & 3) * 2;
            size_t gL = (size_t)(q0 + rL) * HIDN + h * HD + col;
            size_t gH = (size_t)(q0 + rH) * HIDN + h * HD + col;
            float v0 = o_acc[mt][nt][0] * invL, v1 = o_acc[mt][nt][1] * invL;
            float v2 = o_acc[mt][nt][2] * invH, v3 = o_acc[mt][nt][3] * invH;
            __nv_bfloat16 h0 = __float2bfloat16_rn(v0), h1 = __float2bfloat16_rn(v1);
            __nv_bfloat16 h2 = __float2bfloat16_rn(v2), h3 = __float2bfloat16_rn(v3);
            *(__nv_bfloat162*)(Oh + gL) = __halves2bfloat162(h0, h1);
            *(__nv_bfloat162*)(Oh + gH) = __halves2bfloat162(h2, h3);
            *(__nv_bfloat162*)(Ol + gL) = __halves2bfloat162(
                __float2bfloat16_rn(v0 - __bfloat162float(h0)),
                __float2bfloat16_rn(v1 - __bfloat162float(h1)));
            *(__nv_bfloat162*)(Ol + gH) = __halves2bfloat162(
                __float2bfloat16_rn(v2 - __bfloat162float(h2)),
                __float2bfloat16_rn(v3 - __bfloat162float(h3)));
        }
    }
}

// ---------------------------------------------------------------------------
extern "C" void kernel_launch(void* const* d_in, const int* in_sizes, int n_in,
                              void* d_out, int out_size)
{
    const float* hidden = (const float*)d_in[0];
    const float* cosv   = (const float*)d_in[1];
    const float* sinv   = (const float*)d_in[2];
    const float* q_w    = (const float*)d_in[3];
    const float* k_w    = (const float*)d_in[4];
    const float* v_w    = (const float*)d_in[5];
    const float* o_w    = (const float*)d_in[6];
    const float* q_nw   = (const float*)d_in[7];
    const float* k_nw   = (const float*)d_in[8];

    float *qp, *kp, *vp;
    cudaGetSymbolAddress((void**)&qp, g_q);
    cudaGetSymbolAddress((void**)&kp, g_k);
    cudaGetSymbolAddress((void**)&vp, g_v);

    __nv_bfloat16 *hid_h, *hid_l, *qw_h, *qw_l, *kw_h, *kw_l, *vw_h, *vw_l,
                  *ow_h, *ow_l, *at_h, *at_l, *q_h, *q_l, *k_h, *k_l, *v_h, *v_l;
    cudaGetSymbolAddress((void**)&hid_h, sb_hid_hi);
    cudaGetSymbolAddress((void**)&hid_l, sb_hid_lo);
    cudaGetSymbolAddress((void**)&qw_h, sb_qw_hi);
    cudaGetSymbolAddress((void**)&qw_l, sb_qw_lo);
    cudaGetSymbolAddress((void**)&kw_h, sb_kw_hi);
    cudaGetSymbolAddress((void**)&kw_l, sb_kw_lo);
    cudaGetSymbolAddress((void**)&vw_h, sb_vw_hi);
    cudaGetSymbolAddress((void**)&vw_l, sb_vw_lo);
    cudaGetSymbolAddress((void**)&ow_h, sb_ow_hi);
    cudaGetSymbolAddress((void**)&ow_l, sb_ow_lo);
    cudaGetSymbolAddress((void**)&at_h, sb_at_hi);
    cudaGetSymbolAddress((void**)&at_l, sb_at_lo);
    cudaGetSymbolAddress((void**)&q_h, sbq_hi);
    cudaGetSymbolAddress((void**)&q_l, sbq_lo);
    cudaGetSymbolAddress((void**)&k_h, sbk_hi);
    cudaGetSymbolAddress((void**)&k_l, sbk_lo);
    cudaGetSymbolAddress((void**)&v_h, sbv_hi);
    cudaGetSymbolAddress((void**)&v_l, sbv_lo);

    const int gemm_smem = GSTAGES * 4 * GSTG * (int)sizeof(__nv_bfloat16);
    cudaFuncSetAttribute(gemm_bf16split, cudaFuncAttributeMaxDynamicSharedMemorySize,
                         gemm_smem);
    cudaFuncSetAttribute(attn_mma_kernel, cudaFuncAttributeMaxDynamicSharedMemorySize,
                         ATT_SMEM_BYTES);

    auto split = [&](const float* src, __nv_bfloat16* h, __nv_bfloat16* l, int n) {
        int n4 = n / 4;
        split_kernel<<<(n4 + 255) / 256, 256>>>(
            (const float4*)src, (__nv_bfloat162*)h, (__nv_bfloat162*)l, n4);
    };

    // Splits
    split(hidden, hid_h, hid_l, T_TOK * HIDN);
    split(q_w, qw_h, qw_l, HIDN * HIDN);
    split(k_w, kw_h, kw_l, NKV * HD * HIDN);
    split(v_w, vw_h, vw_l, NKV * HD * HIDN);
    split(o_w, ow_h, ow_l, HIDN * HIDN);

    // QKV projections (tensor cores)
    gemm_bf16split<<<dim3(HIDN / GBN, T_TOK / GBM), 256, gemm_smem>>>(
        hid_h, hid_l, qw_h, qw_l, qp, T_TOK, HIDN, HIDN);
    gemm_bf16split<<<dim3(NKV * HD / GBN, T_TOK / GBM), 256, gemm_smem>>>(
        hid_h, hid_l, kw_h, kw_l, kp, T_TOK, NKV * HD, HIDN);
    gemm_bf16split<<<dim3(NKV * HD / GBN, T_TOK / GBM), 256, gemm_smem>>>(
        hid_h, hid_l, vw_h, vw_l, vp, T_TOK, NKV * HD, HIDN);

    // RMSNorm + RoPE -> bf16 hi/lo
    norm_rope_kernel<<<dim3(T_TOK, 16), 256>>>(cosv, sinv, q_nw, k_nw);

    // Attention (tensor cores) -> bf16 hi/lo attn output
    attn_mma_kernel<<<dim3(T_TOK / 64, NH), 256, ATT_SMEM_BYTES>>>(
        q_h, q_l, k_h, k_l, v_h, v_l, at_h, at_l);

    // Output projection
    gemm_bf16split<<<dim3(HIDN / GBN, T_TOK / GBM), 256, gemm_smem>>>(
        at_h, at_l, ow_h, ow_l, (float*)d_out, T_TOK, HIDN, HIDN);
}

// round 7
// speedup vs baseline: 2.3701x; 1.1186x over previous
#include <cuda_runtime.h>
#include <cuda_bf16.h>
#include <stdint.h>
#include <math.h>

// Problem constants
#define T_TOK 4096
#define HIDN  2048
#define NH    8
#define NKV   4
#define HD    256
#define SWIN  1024

// GEMM tiling (2-stage, 2 CTAs/SM)
#define GBK 32
#define GSTRIDE 40
#define GSTG (128 * GSTRIDE)

// Attention smem layout (bf16 element offsets)
#define DS   264
#define PSTR 72
#define ATT_QH 0
#define ATT_QL (64 * DS)
#define ATT_KH (2 * 64 * DS)
#define ATT_KL (3 * 64 * DS)
#define ATT_VH (4 * 64 * DS)
#define ATT_VL (5 * 64 * DS)
#define ATT_PH (6 * 64 * DS)
#define ATT_PL (ATT_PH + 64 * PSTR)
#define ATT_F  (ATT_PL + 64 * PSTR)
#define ATT_SMEM_BYTES (ATT_F * 2 + 448 * 4)

// Scratch (static device globals — allocation-free)
__device__ float g_q[T_TOK * HIDN];
__device__ float g_kv[T_TOK * 2048];      // cols 0..1023 = K, 1024..2047 = V

__device__ __nv_bfloat16 sb_hid_hi[T_TOK * HIDN], sb_hid_lo[T_TOK * HIDN];
__device__ __nv_bfloat16 sb_qw_hi[HIDN * HIDN],   sb_qw_lo[HIDN * HIDN];
__device__ __nv_bfloat16 sb_kvw_hi[HIDN * HIDN],  sb_kvw_lo[HIDN * HIDN];
__device__ __nv_bfloat16 sb_ow_hi[HIDN * HIDN],   sb_ow_lo[HIDN * HIDN];
__device__ __nv_bfloat16 sb_at_hi[T_TOK * HIDN],  sb_at_lo[T_TOK * HIDN];

__device__ __nv_bfloat16 sbq_hi[T_TOK * HIDN],     sbq_lo[T_TOK * HIDN];
__device__ __nv_bfloat16 sbk_hi[T_TOK * NKV * HD], sbk_lo[T_TOK * NKV * HD];
__device__ __nv_bfloat16 sbv_hi[T_TOK * NKV * HD], sbv_lo[T_TOK * NKV * HD];

// ---------------------------------------------------------------------------
#define LDSM4(R, addr) \
    asm volatile("ldmatrix.sync.aligned.m8n8.x4.shared.b16 {%0,%1,%2,%3}, [%4];" \
                 : "=r"((R)[0]), "=r"((R)[1]), "=r"((R)[2]), "=r"((R)[3]) : "r"(addr))

#define LDSM4T(R, addr) \
    asm volatile("ldmatrix.sync.aligned.m8n8.x4.trans.shared.b16 {%0,%1,%2,%3}, [%4];" \
                 : "=r"((R)[0]), "=r"((R)[1]), "=r"((R)[2]), "=r"((R)[3]) : "r"(addr))

#define MMA16816(Cacc, A, b0, b1) \
    asm volatile("mma.sync.aligned.m16n8k16.row.col.f32.bf16.bf16.f32 " \
                 "{%0,%1,%2,%3}, {%4,%5,%6,%7}, {%8,%9}, {%0,%1,%2,%3};" \
                 : "+f"((Cacc)[0]), "+f"((Cacc)[1]), "+f"((Cacc)[2]), "+f"((Cacc)[3]) \
                 : "r"((A)[0]), "r"((A)[1]), "r"((A)[2]), "r"((A)[3]), "r"(b0), "r"(b1))

#define CPA16(dst, src) \
    asm volatile("cp.async.cg.shared.global [%0], [%1], 16;" :: "r"(dst), "l"(src))

__device__ __forceinline__ unsigned int smem_u32(const void* p) {
    return (unsigned int)__cvta_generic_to_shared(p);
}

// ---------------------------------------------------------------------------
// Fused split: all 5 tensors in one launch, 4 float4s per thread (MLP=4).
// Segment boundaries are multiples of 4 float4s, so a thread never crosses one.
// ---------------------------------------------------------------------------
struct SplitSegs {
    const float4* src[5];
    __nv_bfloat162* hi[5];
    __nv_bfloat162* lo[5];
    long end[5];   // cumulative float4 counts
};

__global__ __launch_bounds__(256) void split_all_kernel(SplitSegs segs)
{
    long base = ((long)blockIdx.x * blockDim.x + threadIdx.x) * 4;
    if (base >= segs.end[4]) return;
    int s = 0;
    while (base >= segs.end[s]) ++s;
    long start = (s == 0) ? 0 : segs.end[s - 1];
    long loc = base - start;
    const float4* src = segs.src[s] + loc;
    __nv_bfloat162* hi = segs.hi[s] + 2 * loc;
    __nv_bfloat162* lo = segs.lo[s] + 2 * loc;
#pragma unroll
    for (int j = 0; j < 4; ++j) {
        float4 v = src[j];
        __nv_bfloat16 h0 = __float2bfloat16_rn(v.x);
        __nv_bfloat16 h1 = __float2bfloat16_rn(v.y);
        __nv_bfloat16 h2 = __float2bfloat16_rn(v.z);
        __nv_bfloat16 h3 = __float2bfloat16_rn(v.w);
        hi[2 * j]     = __halves2bfloat162(h0, h1);
        hi[2 * j + 1] = __halves2bfloat162(h2, h3);
        lo[2 * j]     = __halves2bfloat162(
            __float2bfloat16_rn(v.x - __bfloat162float(h0)),
            __float2bfloat16_rn(v.y - __bfloat162float(h1)));
        lo[2 * j + 1] = __halves2bfloat162(
            __float2bfloat16_rn(v.z - __bfloat162float(h2)),
            __float2bfloat16_rn(v.w - __bfloat162float(h3)));
    }
}

// ---------------------------------------------------------------------------
// Split-bf16 tensor-core NT GEMM, 2-stage cp.async, 2 CTAs/SM.
// C[M][N] = A[M][K]*B[N][K]^T; C ~= AhBh + AhBl + AlBh.
// ---------------------------------------------------------------------------
__global__ __launch_bounds__(256, 2) void gemm_bf16split(
    const __nv_bfloat16* __restrict__ Ah, const __nv_bfloat16* __restrict__ Al,
    const __nv_bfloat16* __restrict__ Bh, const __nv_bfloat16* __restrict__ Bl,
    float* __restrict__ C, int M, int N, int K)
{
    extern __shared__ __nv_bfloat16 sm[];
    const int tid = threadIdx.x;
    const int bm = blockIdx.y * 128, bn = blockIdx.x * 128;
    const int lane = tid & 31, wid = tid >> 5;
    const int wm = wid & 3, wn = wid >> 2;

#define GEMM_ISSUE(buf, k0)                                                        \
    {                                                                              \
        __nv_bfloat16* base = sm + (buf) * 4 * GSTG;                               \
        _Pragma("unroll")                                                          \
        for (int half = 0; half < 2; ++half) {                                     \
            int c = tid + half * 256;                                              \
            int row = c >> 2, cc = c & 3;                                          \
            unsigned int sA = smem_u32(base + row * GSTRIDE + cc * 8);             \
            const __nv_bfloat16* gAh = Ah + (size_t)(bm + row) * K + (k0) + cc*8;  \
            const __nv_bfloat16* gAl = Al + (size_t)(bm + row) * K + (k0) + cc*8;  \
            const __nv_bfloat16* gBh = Bh + (size_t)(bn + row) * K + (k0) + cc*8;  \
            const __nv_bfloat16* gBl = Bl + (size_t)(bn + row) * K + (k0) + cc*8;  \
            CPA16(sA, gAh);                                                        \
            CPA16(sA + GSTG * 2, gAl);                                             \
            CPA16(sA + GSTG * 4, gBh);                                             \
            CPA16(sA + GSTG * 6, gBl);                                             \
        }                                                                          \
        asm volatile("cp.async.commit_group;");                                    \
    }

    float acc[16][4];
#pragma unroll
    for (int t = 0; t < 16; ++t)
#pragma unroll
        for (int j = 0; j < 4; ++j) acc[t][j] = 0.f;

    GEMM_ISSUE(0, 0);

    const int iters = K / GBK;
    for (int it = 0; it < iters; ++it) {
        if (it + 1 < iters) {
            GEMM_ISSUE((it + 1) & 1, (it + 1) * GBK);
            asm volatile("cp.async.wait_group 1;");
        } else {
            asm volatile("cp.async.wait_group 0;");
        }
        __syncthreads();

        const __nv_bfloat16* st = sm + (it & 1) * 4 * GSTG;
#pragma unroll
        for (int ks = 0; ks < 2; ++ks) {
            unsigned int ah[2][4], al[2][4];
#pragma unroll
            for (int mt = 0; mt < 2; ++mt) {
                int row = wm * 32 + mt * 16 + (lane & 15);
                int col = ks * 16 + (lane >> 4) * 8;
                unsigned int ad = smem_u32(st + row * GSTRIDE + col);
                LDSM4(ah[mt], ad);
                LDSM4(al[mt], ad + GSTG * 2);
            }
#pragma unroll
            for (int p = 0; p < 4; ++p) {
                int r = lane & 7, g = lane >> 3;
                int nrow = wn * 64 + p * 16 + ((g >> 1) & 1) * 8 + r;
                int col = ks * 16 + (g & 1) * 8;
                unsigned int bd = smem_u32(st + 2 * GSTG + nrow * GSTRIDE + col);
                unsigned int bh[4], bl[4];
                LDSM4(bh, bd);
                LDSM4(bl, bd + GSTG * 2);
#pragma unroll
                for (int mt = 0; mt < 2; ++mt)
#pragma unroll
                    for (int o = 0; o < 4; o += 2) {
                        float* cc = acc[mt * 8 + p * 2 + (o >> 1)];
                        MMA16816(cc, ah[mt], bh[o], bh[o + 1]);
                        MMA16816(cc, ah[mt], bl[o], bl[o + 1]);
                        MMA16816(cc, al[mt], bh[o], bh[o + 1]);
                    }
            }
        }
        __syncthreads();
    }

#pragma unroll
    for (int mt = 0; mt < 2; ++mt)
#pragma unroll
        for (int nt = 0; nt < 8; ++nt) {
            float* cc = acc[mt * 8 + nt];
            int r = bm + wm * 32 + mt * 16 + (lane >> 2);
            int cl = bn + wn * 64 + nt * 8 + (lane & 3) * 2;
            *(float2*)&C[(size_t)r * N + cl]       = make_float2(cc[0], cc[1]);
            *(float2*)&C[(size_t)(r + 8) * N + cl] = make_float2(cc[2], cc[3]);
        }
#undef GEMM_ISSUE
}

// ---------------------------------------------------------------------------
// RMSNorm (+weight) + RoPE, warp-per-role, register-resident rows.
// Block = 1 token, 8 warps x 2 roles. Roles 0-7 q, 8-11 k, 12-15 v.
// ---------------------------------------------------------------------------
__device__ __forceinline__ void store_hl4(__nv_bfloat16* dh, __nv_bfloat16* dl,
                                          size_t off, float4 v)
{
    __nv_bfloat16 h0 = __float2bfloat16_rn(v.x), h1 = __float2bfloat16_rn(v.y);
    __nv_bfloat16 h2 = __float2bfloat16_rn(v.z), h3 = __float2bfloat16_rn(v.w);
    union { __nv_bfloat162 b[2]; uint2 u; } ph, pl;
    ph.b[0] = __halves2bfloat162(h0, h1);
    ph.b[1] = __halves2bfloat162(h2, h3);
    pl.b[0] = __halves2bfloat162(__float2bfloat16_rn(v.x - __bfloat162float(h0)),
                                 __float2bfloat16_rn(v.y - __bfloat162float(h1)));
    pl.b[1] = __halves2bfloat162(__float2bfloat16_rn(v.z - __bfloat162float(h2)),
                                 __float2bfloat16_rn(v.w - __bfloat162float(h3)));
    *(uint2*)(dh + off) = ph.u;
    *(uint2*)(dl + off) = pl.u;
}

__global__ __launch_bounds__(256) void norm_rope_kernel(
    const float* __restrict__ cosv, const float* __restrict__ sinv,
    const float* __restrict__ q_nw, const float* __restrict__ k_nw)
{
    const int t = blockIdx.x;
    const int wid = threadIdx.x >> 5, lane = threadIdx.x & 31;
    const int cA = lane * 4, cB = 128 + lane * 4;

#pragma unroll
    for (int rr = 0; rr < 2; ++rr) {
        const int role = wid * 2 + rr;
        const float* src;
        const float* w = nullptr;
        bool rope = true;
        __nv_bfloat16 *dh, *dl;
        size_t doff;
        if (role < 8) {
            src = g_q + (size_t)t * HIDN + role * HD; w = q_nw;
            dh = sbq_hi; dl = sbq_lo; doff = (size_t)t * HIDN + role * HD;
        } else if (role < 12) {
            src = g_kv + (size_t)t * 2048 + (role - 8) * HD; w = k_nw;
            dh = sbk_hi; dl = sbk_lo; doff = (size_t)t * 1024 + (role - 8) * HD;
        } else {
            src = g_kv + (size_t)t * 2048 + 1024 + (role - 12) * HD; rope = false;
            dh = sbv_hi; dl = sbv_lo; doff = (size_t)t * 1024 + (role - 12) * HD;
        }

        float4 a = *(const float4*)(src + cA);
        float4 b = *(const float4*)(src + cB);
        float ss = a.x*a.x + a.y*a.y + a.z*a.z + a.w*a.w
                 + b.x*b.x + b.y*b.y + b.z*b.z + b.w*b.w;
#pragma unroll
        for (int o = 16; o >= 1; o >>= 1) ss += __shfl_xor_sync(0xffffffffu, ss, o);
        float rn = rsqrtf(ss * (1.f / HD) + 1e-6f);

        float4 ya, yb;
        if (w) {
            float4 wa = *(const float4*)(w + cA);
            float4 wb = *(const float4*)(w + cB);
            ya = make_float4(a.x*rn*wa.x, a.y*rn*wa.y, a.z*rn*wa.z, a.w*rn*wa.w);
            yb = make_float4(b.x*rn*wb.x, b.y*rn*wb.y, b.z*rn*wb.z, b.w*rn*wb.w);
        } else {
            ya = make_float4(a.x*rn, a.y*rn, a.z*rn, a.w*rn);
            yb = make_float4(b.x*rn, b.y*rn, b.z*rn, b.w*rn);
        }

        float4 oa = ya, ob = yb;
        if (rope) {
            const float* cp = cosv + (size_t)t * HD;
            const float* sp = sinv + (size_t)t * HD;
            float4 ca = *(const float4*)(cp + cA), cb = *(const float4*)(cp + cB);
            float4 sa = *(const float4*)(sp + cA), sb = *(const float4*)(sp + cB);
            oa = make_float4(ya.x*ca.x - yb.x*sa.x, ya.y*ca.y - yb.y*sa.y,
                             ya.z*ca.z - yb.z*sa.z, ya.w*ca.w - yb.w*sa.w);
            ob = make_float4(yb.x*cb.x + ya.x*sb.x, yb.y*cb.y + ya.y*sb.y,
                             yb.z*cb.z + ya.z*sb.z, yb.w*cb.w + ya.w*sb.w);
        }
        store_hl4(dh, dl, doff + cA, oa);
        store_hl4(dh, dl, doff + cB, ob);
    }
}

// ---------------------------------------------------------------------------
// Sliding-window flash attention, split-bf16 tensor cores (validated R4).
// ---------------------------------------------------------------------------
__global__ __launch_bounds__(256) void attn_mma_kernel(
    const __nv_bfloat16* __restrict__ Qh, const __nv_bfloat16* __restrict__ Ql,
    const __nv_bfloat16* __restrict__ Kh, const __nv_bfloat16* __restrict__ Kl,
    const __nv_bfloat16* __restrict__ Vh, const __nv_bfloat16* __restrict__ Vl,
    __nv_bfloat16* __restrict__ Oh, __nv_bfloat16* __restrict__ Ol)
{
    extern __shared__ __nv_bfloat16 sm[];
    float* fb     = (float*)(sm + ATT_F);
    float* m_run  = fb;
    float* l_run  = fb + 64;
    float* rscale = fb + 128;
    float* pmax   = fb + 192;
    float* psum   = fb + 320;

    const int qb = blockIdx.x, h = blockIdx.y;
    const int q0 = qb * 64;
    const int kvh = h >> 1;
    const int tid = threadIdx.x;
    const int lane = tid & 31, wid = tid >> 5;
    const int wm = wid & 3, wn = wid >> 2;
    const int wm2 = wid & 1, wn2 = wid >> 1;

    if (tid < 64) { m_run[tid] = -1e30f; l_run[tid] = 0.f; }

    for (int i = tid; i < 2048; i += 256) {
        int r = i >> 5, c = (i & 31) * 8;
        size_t g = (size_t)(q0 + r) * HIDN + h * HD + c;
        CPA16(smem_u32(sm + ATT_QH + r * DS + c), Qh + g);
        CPA16(smem_u32(sm + ATT_QL + r * DS + c), Ql + g);
    }
    asm volatile("cp.async.commit_group;");

    float o_acc[2][8][4];
#pragma unroll
    for (int mt = 0; mt < 2; ++mt)
#pragma unroll
        for (int nt = 0; nt < 8; ++nt)
#pragma unroll
            for (int e = 0; e < 4; ++e) o_acc[mt][nt][e] = 0.f;

    int jmin = q0 - (SWIN - 1); if (jmin < 0) jmin = 0;
    const int t0 = jmin >> 6;
    const int t1 = (q0 + 63) >> 6;

    for (int kt = t0; kt <= t1; ++kt) {
        const int k0 = kt * 64;
        for (int i = tid; i < 2048; i += 256) {
            int r = i >> 5, c = (i & 31) * 8;
            size_t g = (size_t)(k0 + r) * (NKV * HD) + kvh * HD + c;
            CPA16(smem_u32(sm + ATT_KH + r * DS + c), Kh + g);
            CPA16(smem_u32(sm + ATT_KL + r * DS + c), Kl + g);
            CPA16(smem_u32(sm + ATT_VH + r * DS + c), Vh + g);
            CPA16(smem_u32(sm + ATT_VL + r * DS + c), Vl + g);
        }
        asm volatile("cp.async.commit_group;");
        asm volatile("cp.async.wait_group 0;");
        __syncthreads();

        float sacc[4][4];
#pragma unroll
        for (int nt = 0; nt < 4; ++nt)
#pragma unroll
            for (int e = 0; e < 4; ++e) sacc[nt][e] = 0.f;

#pragma unroll 4
        for (int ks = 0; ks < 16; ++ks) {
            unsigned int ah[4], al[4];
            {
                int row = wm * 16 + (lane & 15);
                int col = ks * 16 + (lane >> 4) * 8;
                LDSM4(ah, smem_u32(sm + ATT_QH + row * DS + col));
                LDSM4(al, smem_u32(sm + ATT_QL + row * DS + col));
            }
#pragma unroll
            for (int p = 0; p < 2; ++p) {
                int nrow = wn * 32 + p * 16 + ((lane >> 4) << 3) + (lane & 7);
                int col = ks * 16 + ((lane >> 3) & 1) * 8;
                unsigned int bh[4], bl[4];
                LDSM4(bh, smem_u32(sm + ATT_KH + nrow * DS + col));
                LDSM4(bl, smem_u32(sm + ATT_KL + nrow * DS + col));
#pragma unroll
                for (int o = 0; o < 4; o += 2) {
                    float* cc = sacc[p * 2 + (o >> 1)];
                    MMA16816(cc, ah, bh[o], bh[o + 1]);
                    MMA16816(cc, ah, bl[o], bl[o + 1]);
                    MMA16816(cc, al, bh[o], bh[o + 1]);
                }
            }
        }

        const int r_lo = q0 + wm * 16 + (lane >> 2);
        const int r_hi = r_lo + 8;
#pragma unroll
        for (int nt = 0; nt < 4; ++nt) {
#pragma unroll
            for (int e = 0; e < 2; ++e) {
                int j = k0 + wn * 32 + nt * 8 + (lane & 3) * 2 + e;
                if (!(j <= r_lo && r_lo - j < SWIN)) sacc[nt][e] = -1e30f;
                if (!(j <= r_hi && r_hi - j < SWIN)) sacc[nt][e + 2] = -1e30f;
            }
        }

        float mx0 = -1e30f, mx1 = -1e30f;
#pragma unroll
        for (int nt = 0; nt < 4; ++nt) {
            mx0 = fmaxf(mx0, fmaxf(sacc[nt][0], sacc[nt][1]));
            mx1 = fmaxf(mx1, fmaxf(sacc[nt][2], sacc[nt][3]));
        }
        mx0 = fmaxf(mx0, __shfl_xor_sync(0xffffffffu, mx0, 1));
        mx0 = fmaxf(mx0, __shfl_xor_sync(0xffffffffu, mx0, 2));
        mx1 = fmaxf(mx1, __shfl_xor_sync(0xffffffffu, mx1, 1));
        mx1 = fmaxf(mx1, __shfl_xor_sync(0xffffffffu, mx1, 2));
        if ((lane & 3) == 0) {
            pmax[wn * 64 + wm * 16 + (lane >> 2)]     = mx0;
            pmax[wn * 64 + wm * 16 + 8 + (lane >> 2)] = mx1;
        }
        __syncthreads();

        if (tid < 64) {
            float mo = m_run[tid];
            float mn = fmaxf(mo, fmaxf(pmax[tid], pmax[64 + tid]));
            rscale[tid] = __expf(mo - mn);
            m_run[tid] = mn;
        }
        __syncthreads();

        {
            float m0v = m_run[wm * 16 + (lane >> 2)];
            float m1v = m_run[wm * 16 + 8 + (lane >> 2)];
            float s0 = 0.f, s1 = 0.f;
#pragma unroll
            for (int nt = 0; nt < 4; ++nt) {
                float p00 = (sacc[nt][0] > -1e29f) ? __expf(sacc[nt][0] - m0v) : 0.f;
                float p01 = (sacc[nt][1] > -1e29f) ? __expf(sacc[nt][1] - m0v) : 0.f;
                float p10 = (sacc[nt][2] > -1e29f) ? __expf(sacc[nt][2] - m1v) : 0.f;
                float p11 = (sacc[nt][3] > -1e29f) ? __expf(sacc[nt][3] - m1v) : 0.f;
                s0 += p00 + p01; s1 += p10 + p11;
                int colb = wn * 32 + nt * 8 + (lane & 3) * 2;
                int rowL = wm * 16 + (lane >> 2);
                int rowH = rowL + 8;
                __nv_bfloat16 h00 = __float2bfloat16_rn(p00);
                __nv_bfloat16 h01 = __float2bfloat16_rn(p01);
                __nv_bfloat16 h10 = __float2bfloat16_rn(p10);
                __nv_bfloat16 h11 = __float2bfloat16_rn(p11);
                *(__nv_bfloat162*)(sm + ATT_PH + rowL * PSTR + colb) =
                    __halves2bfloat162(h00, h01);
                *(__nv_bfloat162*)(sm + ATT_PH + rowH * PSTR + colb) =
                    __halves2bfloat162(h10, h11);
                *(__nv_bfloat162*)(sm + ATT_PL + rowL * PSTR + colb) =
                    __halves2bfloat162(
                        __float2bfloat16_rn(p00 - __bfloat162float(h00)),
                        __float2bfloat16_rn(p01 - __bfloat162float(h01)));
                *(__nv_bfloat162*)(sm + ATT_PL + rowH * PSTR + colb) =
                    __halves2bfloat162(
                        __float2bfloat16_rn(p10 - __bfloat162float(h10)),
                        __float2bfloat16_rn(p11 - __bfloat162float(h11)));
            }
            s0 += __shfl_xor_sync(0xffffffffu, s0, 1);
            s0 += __shfl_xor_sync(0xffffffffu, s0, 2);
            s1 += __shfl_xor_sync(0xffffffffu, s1, 1);
            s1 += __shfl_xor_sync(0xffffffffu, s1, 2);
            if ((lane & 3) == 0) {
                psum[wn * 64 + wm * 16 + (lane >> 2)]     = s0;
                psum[wn * 64 + wm * 16 + 8 + (lane >> 2)] = s1;
            }
        }
        __syncthreads();

        if (tid < 64)
            l_run[tid] = l_run[tid] * rscale[tid] + psum[tid] + psum[64 + tid];

#pragma unroll
        for (int mt = 0; mt < 2; ++mt) {
            float sL = rscale[wm2 * 32 + mt * 16 + (lane >> 2)];
            float sH = rscale[wm2 * 32 + mt * 16 + 8 + (lane >> 2)];
#pragma unroll
            for (int nt = 0; nt < 8; ++nt) {
                o_acc[mt][nt][0] *= sL; o_acc[mt][nt][1] *= sL;
                o_acc[mt][nt][2] *= sH; o_acc[mt][nt][3] *= sH;
            }
        }

#pragma unroll
        for (int ks2 = 0; ks2 < 4; ++ks2) {
            unsigned int aph[2][4], apl[2][4];
#pragma unroll
            for (int mt = 0; mt < 2; ++mt) {
                int row = wm2 * 32 + mt * 16 + (lane & 15);
                int col = ks2 * 16 + (lane >> 4) * 8;
                LDSM4(aph[mt], smem_u32(sm + ATT_PH + row * PSTR + col));
                LDSM4(apl[mt], smem_u32(sm + ATT_PL + row * PSTR + col));
            }
#pragma unroll
            for (int ng = 0; ng < 4; ++ng) {
                int vr = ks2 * 16 + ((lane >> 3) & 1) * 8 + (lane & 7);
                int vc = wn2 * 64 + ng * 16 + (lane >> 4) * 8;
                unsigned int bvh[4], bvl[4];
                LDSM4T(bvh, smem_u32(sm + ATT_VH + vr * DS + vc));
                LDSM4T(bvl, smem_u32(sm + ATT_VL + vr * DS + vc));
#pragma unroll
                for (int mt = 0; mt < 2; ++mt)
#pragma unroll
                    for (int o = 0; o < 4; o += 2) {
                        float* cc = o_acc[mt][ng * 2 + (o >> 1)];
                        MMA16816(cc, aph[mt], bvh[o], bvh[o + 1]);
                        MMA16816(cc, aph[mt], bvl[o], bvl[o + 1]);
                        MMA16816(cc, apl[mt], bvh[o], bvh[o + 1]);
                    }
            }
        }
        __syncthreads();
    }

#pragma unroll
    for (int mt = 0; mt < 2; ++mt) {
        int rL = wm2 * 32 + mt * 16 + (lane >> 2);
        int rH = rL + 8;
        float invL = 1.f / l_run[rL];
        float invH = 1.f / l_run[rH];
#pragma unroll
        for (int nt = 0; nt < 8; ++nt) {
            int col = wn2 * 64 + nt * 8 + (lane & 3) * 2;
            size_t gL = (size_t)(q0 + rL) * HIDN + h * HD + col;
            size_t gH = (size_t)(q0 + rH) * HIDN + h * HD + col;
            float v0 = o_acc[mt][nt][0] * invL, v1 = o_acc[mt][nt][1] * invL;
            float v2 = o_acc[mt][nt][2] * invH, v3 = o_acc[mt][nt][3] * invH;
            __nv_bfloat16 h0 = __float2bfloat16_rn(v0), h1 = __float2bfloat16_rn(v1);
            __nv_bfloat16 h2 = __float2bfloat16_rn(v2), h3 = __float2bfloat16_rn(v3);
            *(__nv_bfloat162*)(Oh + gL) = __halves2bfloat162(h0, h1);
            *(__nv_bfloat162*)(Oh + gH) = __halves2bfloat162(h2, h3);
            *(__nv_bfloat162*)(Ol + gL) = __halves2bfloat162(
                __float2bfloat16_rn(v0 - __bfloat162float(h0)),
                __float2bfloat16_rn(v1 - __bfloat162float(h1)));
            *(__nv_bfloat162*)(Ol + gH) = __halves2bfloat162(
                __float2bfloat16_rn(v2 - __bfloat162float(h2)),
                __float2bfloat16_rn(v3 - __bfloat162float(h3)));
        }
    }
}

// ---------------------------------------------------------------------------
extern "C" void kernel_launch(void* const* d_in, const int* in_sizes, int n_in,
                              void* d_out, int out_size)
{
    const float* hidden = (const float*)d_in[0];
    const float* cosv   = (const float*)d_in[1];
    const float* sinv   = (const float*)d_in[2];
    const float* q_w    = (const float*)d_in[3];
    const float* k_w    = (const float*)d_in[4];
    const float* v_w    = (const float*)d_in[5];
    const float* o_w    = (const float*)d_in[6];
    const float* q_nw   = (const float*)d_in[7];
    const float* k_nw   = (const float*)d_in[8];

    float *qp, *kvp;
    cudaGetSymbolAddress((void**)&qp, g_q);
    cudaGetSymbolAddress((void**)&kvp, g_kv);

    __nv_bfloat16 *hid_h, *hid_l, *qw_h, *qw_l, *kvw_h, *kvw_l,
                  *ow_h, *ow_l, *at_h, *at_l, *q_h, *q_l, *k_h, *k_l, *v_h, *v_l;
    cudaGetSymbolAddress((void**)&hid_h, sb_hid_hi);
    cudaGetSymbolAddress((void**)&hid_l, sb_hid_lo);
    cudaGetSymbolAddress((void**)&qw_h, sb_qw_hi);
    cudaGetSymbolAddress((void**)&qw_l, sb_qw_lo);
    cudaGetSymbolAddress((void**)&kvw_h, sb_kvw_hi);
    cudaGetSymbolAddress((void**)&kvw_l, sb_kvw_lo);
    cudaGetSymbolAddress((void**)&ow_h, sb_ow_hi);
    cudaGetSymbolAddress((void**)&ow_l, sb_ow_lo);
    cudaGetSymbolAddress((void**)&at_h, sb_at_hi);
    cudaGetSymbolAddress((void**)&at_l, sb_at_lo);
    cudaGetSymbolAddress((void**)&q_h, sbq_hi);
    cudaGetSymbolAddress((void**)&q_l, sbq_lo);
    cudaGetSymbolAddress((void**)&k_h, sbk_hi);
    cudaGetSymbolAddress((void**)&k_l, sbk_lo);
    cudaGetSymbolAddress((void**)&v_h, sbv_hi);
    cudaGetSymbolAddress((void**)&v_l, sbv_lo);

    const int gemm_smem = 2 * 4 * GSTG * (int)sizeof(__nv_bfloat16);  // 81,920
    cudaFuncSetAttribute(gemm_bf16split, cudaFuncAttributeMaxDynamicSharedMemorySize,
                         gemm_smem);
    cudaFuncSetAttribute(attn_mma_kernel, cudaFuncAttributeMaxDynamicSharedMemorySize,
                         ATT_SMEM_BYTES);

    // Fused split of all five fp32 tensors -> bf16 hi/lo
    SplitSegs segs;
    long n_hid = (long)T_TOK * HIDN / 4;          // 2,097,152
    long n_qw  = (long)HIDN * HIDN / 4;           // 1,048,576
    long n_kw  = (long)NKV * HD * HIDN / 4;       //   524,288
    segs.src[0] = (const float4*)hidden; segs.hi[0] = (__nv_bfloat162*)hid_h;
    segs.lo[0] = (__nv_bfloat162*)hid_l; segs.end[0] = n_hid;
    segs.src[1] = (const float4*)q_w;    segs.hi[1] = (__nv_bfloat162*)qw_h;
    segs.lo[1] = (__nv_bfloat162*)qw_l;  segs.end[1] = segs.end[0] + n_qw;
    segs.src[2] = (const float4*)k_w;    segs.hi[2] = (__nv_bfloat162*)kvw_h;
    segs.lo[2] = (__nv_bfloat162*)kvw_l; segs.end[2] = segs.end[1] + n_kw;
    segs.src[3] = (const float4*)v_w;
    segs.hi[3] = (__nv_bfloat162*)(kvw_h + (size_t)NKV * HD * HIDN);
    segs.lo[3] = (__nv_bfloat162*)(kvw_l + (size_t)NKV * HD * HIDN);
    segs.end[3] = segs.end[2] + n_kw;
    segs.src[4] = (const float4*)o_w;    segs.hi[4] = (__nv_bfloat162*)ow_h;
    segs.lo[4] = (__nv_bfloat162*)ow_l;  segs.end[4] = segs.end[3] + n_qw;
    long total_thr = segs.end[4] / 4;
    split_all_kernel<<<(unsigned)((total_thr + 255) / 256), 256>>>(segs);

    // Q projection and fused K+V projection (2 CTAs/SM)
    gemm_bf16split<<<dim3(HIDN / 128, T_TOK / 128), 256, gemm_smem>>>(
        hid_h, hid_l, qw_h, qw_l, qp, T_TOK, HIDN, HIDN);
    gemm_bf16split<<<dim3(2048 / 128, T_TOK / 128), 256, gemm_smem>>>(
        hid_h, hid_l, kvw_h, kvw_l, kvp, T_TOK, 2048, HIDN);

    // RMSNorm + RoPE -> bf16 hi/lo
    norm_rope_kernel<<<T_TOK, 256>>>(cosv, sinv, q_nw, k_nw);

    // Attention
    attn_mma_kernel<<<dim3(T_TOK / 64, NH), 256, ATT_SMEM_BYTES>>>(
        q_h, q_l, k_h, k_l, v_h, v_l, at_h, at_l);

    // Output projection
    gemm_bf16split<<<dim3(HIDN / 128, T_TOK / 128), 256, gemm_smem>>>(
        at_h, at_l, ow_h, ow_l, (float*)d_out, T_TOK, HIDN, HIDN);
}

// round 8
// speedup vs baseline: 2.5248x; 1.0653x over previous
#include <cuda_runtime.h>
#include <cuda_bf16.h>
#include <stdint.h>
#include <math.h>

// Problem constants
#define T_TOK 4096
#define HIDN  2048
#define NH    8
#define NKV   4
#define HD    256
#define SWIN  1024

// GEMM tiling (2-stage, 2 CTAs/SM)
#define GBK 32
#define GSTRIDE 40
#define GSTG (128 * GSTRIDE)

// Attention smem layout (bf16 element offsets)
#define DS   264
#define PSTR 72
#define ATT_QH 0
#define ATT_QL (64 * DS)
#define ATT_KH (2 * 64 * DS)
#define ATT_KL (3 * 64 * DS)
#define ATT_VH (4 * 64 * DS)
#define ATT_VL (5 * 64 * DS)
#define ATT_PH (6 * 64 * DS)
#define ATT_PL (ATT_PH + 64 * PSTR)
#define ATT_F  (ATT_PL + 64 * PSTR)
#define ATT_SMEM_BYTES (ATT_F * 2 + 448 * 4)

// Scratch (static device globals — allocation-free)
__device__ float g_qkv[T_TOK * 4096];   // cols 0-2047 q, 2048-3071 k, 3072-4095 v

__device__ __nv_bfloat16 sb_hid_hi[T_TOK * HIDN], sb_hid_lo[T_TOK * HIDN];
__device__ __nv_bfloat16 sb_w_hi[4096 * HIDN],    sb_w_lo[4096 * HIDN];  // [q;k;v]
__device__ __nv_bfloat16 sb_ow_hi[HIDN * HIDN],   sb_ow_lo[HIDN * HIDN];
__device__ __nv_bfloat16 sb_at_hi[T_TOK * HIDN],  sb_at_lo[T_TOK * HIDN];

__device__ __nv_bfloat16 sbq_hi[T_TOK * HIDN],     sbq_lo[T_TOK * HIDN];
__device__ __nv_bfloat16 sbk_hi[T_TOK * NKV * HD], sbk_lo[T_TOK * NKV * HD];
__device__ __nv_bfloat16 sbv_hi[T_TOK * NKV * HD], sbv_lo[T_TOK * NKV * HD];

// ---------------------------------------------------------------------------
#define LDSM4(R, addr) \
    asm volatile("ldmatrix.sync.aligned.m8n8.x4.shared.b16 {%0,%1,%2,%3}, [%4];" \
                 : "=r"((R)[0]), "=r"((R)[1]), "=r"((R)[2]), "=r"((R)[3]) : "r"(addr))

#define LDSM4T(R, addr) \
    asm volatile("ldmatrix.sync.aligned.m8n8.x4.trans.shared.b16 {%0,%1,%2,%3}, [%4];" \
                 : "=r"((R)[0]), "=r"((R)[1]), "=r"((R)[2]), "=r"((R)[3]) : "r"(addr))

#define MMA16816(Cacc, A, b0, b1) \
    asm volatile("mma.sync.aligned.m16n8k16.row.col.f32.bf16.bf16.f32 " \
                 "{%0,%1,%2,%3}, {%4,%5,%6,%7}, {%8,%9}, {%0,%1,%2,%3};" \
                 : "+f"((Cacc)[0]), "+f"((Cacc)[1]), "+f"((Cacc)[2]), "+f"((Cacc)[3]) \
                 : "r"((A)[0]), "r"((A)[1]), "r"((A)[2]), "r"((A)[3]), "r"(b0), "r"(b1))

#define CPA16(dst, src) \
    asm volatile("cp.async.cg.shared.global [%0], [%1], 16;" :: "r"(dst), "l"(src))

__device__ __forceinline__ unsigned int smem_u32(const void* p) {
    return (unsigned int)__cvta_generic_to_shared(p);
}

// ---------------------------------------------------------------------------
// Fused split: all 5 tensors in one launch, 4 float4s per thread (MLP=4).
// ---------------------------------------------------------------------------
struct SplitSegs {
    const float4* src[5];
    __nv_bfloat162* hi[5];
    __nv_bfloat162* lo[5];
    long end[5];
};

__global__ __launch_bounds__(256) void split_all_kernel(SplitSegs segs)
{
    long base = ((long)blockIdx.x * blockDim.x + threadIdx.x) * 4;
    if (base >= segs.end[4]) return;
    int s = 0;
    while (base >= segs.end[s]) ++s;
    long start = (s == 0) ? 0 : segs.end[s - 1];
    long loc = base - start;
    const float4* src = segs.src[s] + loc;
    __nv_bfloat162* hi = segs.hi[s] + 2 * loc;
    __nv_bfloat162* lo = segs.lo[s] + 2 * loc;
#pragma unroll
    for (int j = 0; j < 4; ++j) {
        float4 v = src[j];
        __nv_bfloat16 h0 = __float2bfloat16_rn(v.x);
        __nv_bfloat16 h1 = __float2bfloat16_rn(v.y);
        __nv_bfloat16 h2 = __float2bfloat16_rn(v.z);
        __nv_bfloat16 h3 = __float2bfloat16_rn(v.w);
        hi[2 * j]     = __halves2bfloat162(h0, h1);
        hi[2 * j + 1] = __halves2bfloat162(h2, h3);
        lo[2 * j]     = __halves2bfloat162(
            __float2bfloat16_rn(v.x - __bfloat162float(h0)),
            __float2bfloat16_rn(v.y - __bfloat162float(h1)));
        lo[2 * j + 1] = __halves2bfloat162(
            __float2bfloat16_rn(v.z - __bfloat162float(h2)),
            __float2bfloat16_rn(v.w - __bfloat162float(h3)));
    }
}

// ---------------------------------------------------------------------------
// Split-bf16 tensor-core NT GEMM, 2-stage cp.async, 2 CTAs/SM (validated R7).
// ---------------------------------------------------------------------------
__global__ __launch_bounds__(256, 2) void gemm_bf16split(
    const __nv_bfloat16* __restrict__ Ah, const __nv_bfloat16* __restrict__ Al,
    const __nv_bfloat16* __restrict__ Bh, const __nv_bfloat16* __restrict__ Bl,
    float* __restrict__ C, int M, int N, int K)
{
    extern __shared__ __nv_bfloat16 sm[];
    const int tid = threadIdx.x;
    const int bm = blockIdx.y * 128, bn = blockIdx.x * 128;
    const int lane = tid & 31, wid = tid >> 5;
    const int wm = wid & 3, wn = wid >> 2;

#define GEMM_ISSUE(buf, k0)                                                        \
    {                                                                              \
        __nv_bfloat16* base = sm + (buf) * 4 * GSTG;                               \
        _Pragma("unroll")                                                          \
        for (int half = 0; half < 2; ++half) {                                     \
            int c = tid + half * 256;                                              \
            int row = c >> 2, cc = c & 3;                                          \
            unsigned int sA = smem_u32(base + row * GSTRIDE + cc * 8);             \
            const __nv_bfloat16* gAh = Ah + (size_t)(bm + row) * K + (k0) + cc*8;  \
            const __nv_bfloat16* gAl = Al + (size_t)(bm + row) * K + (k0) + cc*8;  \
            const __nv_bfloat16* gBh = Bh + (size_t)(bn + row) * K + (k0) + cc*8;  \
            const __nv_bfloat16* gBl = Bl + (size_t)(bn + row) * K + (k0) + cc*8;  \
            CPA16(sA, gAh);                                                        \
            CPA16(sA + GSTG * 2, gAl);                                             \
            CPA16(sA + GSTG * 4, gBh);                                             \
            CPA16(sA + GSTG * 6, gBl);                                             \
        }                                                                          \
        asm volatile("cp.async.commit_group;");                                    \
    }

    float acc[16][4];
#pragma unroll
    for (int t = 0; t < 16; ++t)
#pragma unroll
        for (int j = 0; j < 4; ++j) acc[t][j] = 0.f;

    GEMM_ISSUE(0, 0);

    const int iters = K / GBK;
    for (int it = 0; it < iters; ++it) {
        if (it + 1 < iters) {
            GEMM_ISSUE((it + 1) & 1, (it + 1) * GBK);
            asm volatile("cp.async.wait_group 1;");
        } else {
            asm volatile("cp.async.wait_group 0;");
        }
        __syncthreads();

        const __nv_bfloat16* st = sm + (it & 1) * 4 * GSTG;
#pragma unroll
        for (int ks = 0; ks < 2; ++ks) {
            unsigned int ah[2][4], al[2][4];
#pragma unroll
            for (int mt = 0; mt < 2; ++mt) {
                int row = wm * 32 + mt * 16 + (lane & 15);
                int col = ks * 16 + (lane >> 4) * 8;
                unsigned int ad = smem_u32(st + row * GSTRIDE + col);
                LDSM4(ah[mt], ad);
                LDSM4(al[mt], ad + GSTG * 2);
            }
#pragma unroll
            for (int p = 0; p < 4; ++p) {
                int r = lane & 7, g = lane >> 3;
                int nrow = wn * 64 + p * 16 + ((g >> 1) & 1) * 8 + r;
                int col = ks * 16 + (g & 1) * 8;
                unsigned int bd = smem_u32(st + 2 * GSTG + nrow * GSTRIDE + col);
                unsigned int bh[4], bl[4];
                LDSM4(bh, bd);
                LDSM4(bl, bd + GSTG * 2);
#pragma unroll
                for (int mt = 0; mt < 2; ++mt)
#pragma unroll
                    for (int o = 0; o < 4; o += 2) {
                        float* cc = acc[mt * 8 + p * 2 + (o >> 1)];
                        MMA16816(cc, ah[mt], bh[o], bh[o + 1]);
                        MMA16816(cc, ah[mt], bl[o], bl[o + 1]);
                        MMA16816(cc, al[mt], bh[o], bh[o + 1]);
                    }
            }
        }
        __syncthreads();
    }

#pragma unroll
    for (int mt = 0; mt < 2; ++mt)
#pragma unroll
        for (int nt = 0; nt < 8; ++nt) {
            float* cc = acc[mt * 8 + nt];
            int r = bm + wm * 32 + mt * 16 + (lane >> 2);
            int cl = bn + wn * 64 + nt * 8 + (lane & 3) * 2;
            *(float2*)&C[(size_t)r * N + cl]       = make_float2(cc[0], cc[1]);
            *(float2*)&C[(size_t)(r + 8) * N + cl] = make_float2(cc[2], cc[3]);
        }
#undef GEMM_ISSUE
}

// ---------------------------------------------------------------------------
// RMSNorm (+weight) + RoPE, warp-per-role (reads fused g_qkv).
// ---------------------------------------------------------------------------
__device__ __forceinline__ void store_hl4(__nv_bfloat16* dh, __nv_bfloat16* dl,
                                          size_t off, float4 v)
{
    __nv_bfloat16 h0 = __float2bfloat16_rn(v.x), h1 = __float2bfloat16_rn(v.y);
    __nv_bfloat16 h2 = __float2bfloat16_rn(v.z), h3 = __float2bfloat16_rn(v.w);
    union { __nv_bfloat162 b[2]; uint2 u; } ph, pl;
    ph.b[0] = __halves2bfloat162(h0, h1);
    ph.b[1] = __halves2bfloat162(h2, h3);
    pl.b[0] = __halves2bfloat162(__float2bfloat16_rn(v.x - __bfloat162float(h0)),
                                 __float2bfloat16_rn(v.y - __bfloat162float(h1)));
    pl.b[1] = __halves2bfloat162(__float2bfloat16_rn(v.z - __bfloat162float(h2)),
                                 __float2bfloat16_rn(v.w - __bfloat162float(h3)));
    *(uint2*)(dh + off) = ph.u;
    *(uint2*)(dl + off) = pl.u;
}

__global__ __launch_bounds__(256) void norm_rope_kernel(
    const float* __restrict__ cosv, const float* __restrict__ sinv,
    const float* __restrict__ q_nw, const float* __restrict__ k_nw)
{
    const int t = blockIdx.x;
    const int wid = threadIdx.x >> 5, lane = threadIdx.x & 31;
    const int cA = lane * 4, cB = 128 + lane * 4;

#pragma unroll
    for (int rr = 0; rr < 2; ++rr) {
        const int role = wid * 2 + rr;
        const float* src;
        const float* w = nullptr;
        bool rope = true;
        __nv_bfloat16 *dh, *dl;
        size_t doff;
        if (role < 8) {
            src = g_qkv + (size_t)t * 4096 + role * HD; w = q_nw;
            dh = sbq_hi; dl = sbq_lo; doff = (size_t)t * HIDN + role * HD;
        } else if (role < 12) {
            src = g_qkv + (size_t)t * 4096 + 2048 + (role - 8) * HD; w = k_nw;
            dh = sbk_hi; dl = sbk_lo; doff = (size_t)t * 1024 + (role - 8) * HD;
        } else {
            src = g_qkv + (size_t)t * 4096 + 3072 + (role - 12) * HD; rope = false;
            dh = sbv_hi; dl = sbv_lo; doff = (size_t)t * 1024 + (role - 12) * HD;
        }

        float4 a = *(const float4*)(src + cA);
        float4 b = *(const float4*)(src + cB);
        float ss = a.x*a.x + a.y*a.y + a.z*a.z + a.w*a.w
                 + b.x*b.x + b.y*b.y + b.z*b.z + b.w*b.w;
#pragma unroll
        for (int o = 16; o >= 1; o >>= 1) ss += __shfl_xor_sync(0xffffffffu, ss, o);
        float rn = rsqrtf(ss * (1.f / HD) + 1e-6f);

        float4 ya, yb;
        if (w) {
            float4 wa = *(const float4*)(w + cA);
            float4 wb = *(const float4*)(w + cB);
            ya = make_float4(a.x*rn*wa.x, a.y*rn*wa.y, a.z*rn*wa.z, a.w*rn*wa.w);
            yb = make_float4(b.x*rn*wb.x, b.y*rn*wb.y, b.z*rn*wb.z, b.w*rn*wb.w);
        } else {
            ya = make_float4(a.x*rn, a.y*rn, a.z*rn, a.w*rn);
            yb = make_float4(b.x*rn, b.y*rn, b.z*rn, b.w*rn);
        }

        float4 oa = ya, ob = yb;
        if (rope) {
            const float* cp = cosv + (size_t)t * HD;
            const float* sp = sinv + (size_t)t * HD;
            float4 ca = *(const float4*)(cp + cA), cb = *(const float4*)(cp + cB);
            float4 sa = *(const float4*)(sp + cA), sb = *(const float4*)(sp + cB);
            oa = make_float4(ya.x*ca.x - yb.x*sa.x, ya.y*ca.y - yb.y*sa.y,
                             ya.z*ca.z - yb.z*sa.z, ya.w*ca.w - yb.w*sa.w);
            ob = make_float4(yb.x*cb.x + ya.x*sb.x, yb.y*cb.y + ya.y*sb.y,
                             yb.z*cb.z + ya.z*sb.z, yb.w*cb.w + ya.w*sb.w);
        }
        store_hl4(dh, dl, doff + cA, oa);
        store_hl4(dh, dl, doff + cB, ob);
    }
}

// ---------------------------------------------------------------------------
// Sliding-window flash attention with pipelined K/V loads.
// K(t+1) issued after phase-1 barrier; V(t+1) after phase-2 barrier.
// ---------------------------------------------------------------------------
__global__ __launch_bounds__(256) void attn_mma_kernel(
    const __nv_bfloat16* __restrict__ Qh, const __nv_bfloat16* __restrict__ Ql,
    const __nv_bfloat16* __restrict__ Kh, const __nv_bfloat16* __restrict__ Kl,
    const __nv_bfloat16* __restrict__ Vh, const __nv_bfloat16* __restrict__ Vl,
    __nv_bfloat16* __restrict__ Oh, __nv_bfloat16* __restrict__ Ol)
{
    extern __shared__ __nv_bfloat16 sm[];
    float* fb     = (float*)(sm + ATT_F);
    float* m_run  = fb;
    float* l_run  = fb + 64;
    float* rscale = fb + 128;
    float* pmax   = fb + 192;
    float* psum   = fb + 320;

    const int qb = blockIdx.x, h = blockIdx.y;
    const int q0 = qb * 64;
    const int kvh = h >> 1;
    const int tid = threadIdx.x;
    const int lane = tid & 31, wid = tid >> 5;
    const int wm = wid & 3, wn = wid >> 2;
    const int wm2 = wid & 1, wn2 = wid >> 1;

    if (tid < 64) { m_run[tid] = -1e30f; l_run[tid] = 0.f; }

#define ISSUE_K(k0)                                                            \
    {                                                                          \
        for (int i = tid; i < 2048; i += 256) {                                \
            int r = i >> 5, c = (i & 31) * 8;                                  \
            size_t g = (size_t)((k0) + r) * (NKV * HD) + kvh * HD + c;         \
            CPA16(smem_u32(sm + ATT_KH + r * DS + c), Kh + g);                 \
            CPA16(smem_u32(sm + ATT_KL + r * DS + c), Kl + g);                 \
        }                                                                      \
        asm volatile("cp.async.commit_group;");                                \
    }
#define ISSUE_V(k0)                                                            \
    {                                                                          \
        for (int i = tid; i < 2048; i += 256) {                                \
            int r = i >> 5, c = (i & 31) * 8;                                  \
            size_t g = (size_t)((k0) + r) * (NKV * HD) + kvh * HD + c;         \
            CPA16(smem_u32(sm + ATT_VH + r * DS + c), Vh + g);                 \
            CPA16(smem_u32(sm + ATT_VL + r * DS + c), Vl + g);                 \
        }                                                                      \
        asm volatile("cp.async.commit_group;");                                \
    }

    // Prologue: Q, K(t0), V(t0)
    for (int i = tid; i < 2048; i += 256) {
        int r = i >> 5, c = (i & 31) * 8;
        size_t g = (size_t)(q0 + r) * HIDN + h * HD + c;
        CPA16(smem_u32(sm + ATT_QH + r * DS + c), Qh + g);
        CPA16(smem_u32(sm + ATT_QL + r * DS + c), Ql + g);
    }
    asm volatile("cp.async.commit_group;");

    float o_acc[2][8][4];
#pragma unroll
    for (int mt = 0; mt < 2; ++mt)
#pragma unroll
        for (int nt = 0; nt < 8; ++nt)
#pragma unroll
            for (int e = 0; e < 4; ++e) o_acc[mt][nt][e] = 0.f;

    int jmin = q0 - (SWIN - 1); if (jmin < 0) jmin = 0;
    const int t0 = jmin >> 6;
    const int t1 = (q0 + 63) >> 6;

    ISSUE_K(t0 * 64);
    ISSUE_V(t0 * 64);
    asm volatile("cp.async.wait_group 1;");   // Q + K0 done (V0 may pend)
    __syncthreads();

    for (int kt = t0; kt <= t1; ++kt) {
        const int k0 = kt * 64;

        // ---- Phase 1: S = Q K^T ----
        float sacc[4][4];
#pragma unroll
        for (int nt = 0; nt < 4; ++nt)
#pragma unroll
            for (int e = 0; e < 4; ++e) sacc[nt][e] = 0.f;

#pragma unroll 4
        for (int ks = 0; ks < 16; ++ks) {
            unsigned int ah[4], al[4];
            {
                int row = wm * 16 + (lane & 15);
                int col = ks * 16 + (lane >> 4) * 8;
                LDSM4(ah, smem_u32(sm + ATT_QH + row * DS + col));
                LDSM4(al, smem_u32(sm + ATT_QL + row * DS + col));
            }
#pragma unroll
            for (int p = 0; p < 2; ++p) {
                int nrow = wn * 32 + p * 16 + ((lane >> 4) << 3) + (lane & 7);
                int col = ks * 16 + ((lane >> 3) & 1) * 8;
                unsigned int bh[4], bl[4];
                LDSM4(bh, smem_u32(sm + ATT_KH + nrow * DS + col));
                LDSM4(bl, smem_u32(sm + ATT_KL + nrow * DS + col));
#pragma unroll
                for (int o = 0; o < 4; o += 2) {
                    float* cc = sacc[p * 2 + (o >> 1)];
                    MMA16816(cc, ah, bh[o], bh[o + 1]);
                    MMA16816(cc, ah, bl[o], bl[o + 1]);
                    MMA16816(cc, al, bh[o], bh[o + 1]);
                }
            }
        }

        // Mask
        const int r_lo = q0 + wm * 16 + (lane >> 2);
        const int r_hi = r_lo + 8;
#pragma unroll
        for (int nt = 0; nt < 4; ++nt) {
#pragma unroll
            for (int e = 0; e < 2; ++e) {
                int j = k0 + wn * 32 + nt * 8 + (lane & 3) * 2 + e;
                if (!(j <= r_lo && r_lo - j < SWIN)) sacc[nt][e] = -1e30f;
                if (!(j <= r_hi && r_hi - j < SWIN)) sacc[nt][e + 2] = -1e30f;
            }
        }

        float mx0 = -1e30f, mx1 = -1e30f;
#pragma unroll
        for (int nt = 0; nt < 4; ++nt) {
            mx0 = fmaxf(mx0, fmaxf(sacc[nt][0], sacc[nt][1]));
            mx1 = fmaxf(mx1, fmaxf(sacc[nt][2], sacc[nt][3]));
        }
        mx0 = fmaxf(mx0, __shfl_xor_sync(0xffffffffu, mx0, 1));
        mx0 = fmaxf(mx0, __shfl_xor_sync(0xffffffffu, mx0, 2));
        mx1 = fmaxf(mx1, __shfl_xor_sync(0xffffffffu, mx1, 1));
        mx1 = fmaxf(mx1, __shfl_xor_sync(0xffffffffu, mx1, 2));
        if ((lane & 3) == 0) {
            pmax[wn * 64 + wm * 16 + (lane >> 2)]     = mx0;
            pmax[wn * 64 + wm * 16 + 8 + (lane >> 2)] = mx1;
        }
        __syncthreads();          // all warps done with K tile

        // Prefetch next K while softmax + PV run
        if (kt < t1) ISSUE_K(k0 + 64);

        if (tid < 64) {
            float mo = m_run[tid];
            float mn = fmaxf(mo, fmaxf(pmax[tid], pmax[64 + tid]));
            rscale[tid] = __expf(mo - mn);
            m_run[tid] = mn;
        }
        __syncthreads();

        {
            float m0v = m_run[wm * 16 + (lane >> 2)];
            float m1v = m_run[wm * 16 + 8 + (lane >> 2)];
            float s0 = 0.f, s1 = 0.f;
#pragma unroll
            for (int nt = 0; nt < 4; ++nt) {
                float p00 = (sacc[nt][0] > -1e29f) ? __expf(sacc[nt][0] - m0v) : 0.f;
                float p01 = (sacc[nt][1] > -1e29f) ? __expf(sacc[nt][1] - m0v) : 0.f;
                float p10 = (sacc[nt][2] > -1e29f) ? __expf(sacc[nt][2] - m1v) : 0.f;
                float p11 = (sacc[nt][3] > -1e29f) ? __expf(sacc[nt][3] - m1v) : 0.f;
                s0 += p00 + p01; s1 += p10 + p11;
                int colb = wn * 32 + nt * 8 + (lane & 3) * 2;
                int rowL = wm * 16 + (lane >> 2);
                int rowH = rowL + 8;
                __nv_bfloat16 h00 = __float2bfloat16_rn(p00);
                __nv_bfloat16 h01 = __float2bfloat16_rn(p01);
                __nv_bfloat16 h10 = __float2bfloat16_rn(p10);
                __nv_bfloat16 h11 = __float2bfloat16_rn(p11);
                *(__nv_bfloat162*)(sm + ATT_PH + rowL * PSTR + colb) =
                    __halves2bfloat162(h00, h01);
                *(__nv_bfloat162*)(sm + ATT_PH + rowH * PSTR + colb) =
                    __halves2bfloat162(h10, h11);
                *(__nv_bfloat162*)(sm + ATT_PL + rowL * PSTR + colb) =
                    __halves2bfloat162(
                        __float2bfloat16_rn(p00 - __bfloat162float(h00)),
                        __float2bfloat16_rn(p01 - __bfloat162float(h01)));
                *(__nv_bfloat162*)(sm + ATT_PL + rowH * PSTR + colb) =
                    __halves2bfloat162(
                        __float2bfloat16_rn(p10 - __bfloat162float(h10)),
                        __float2bfloat16_rn(p11 - __bfloat162float(h11)));
            }
            s0 += __shfl_xor_sync(0xffffffffu, s0, 1);
            s0 += __shfl_xor_sync(0xffffffffu, s0, 2);
            s1 += __shfl_xor_sync(0xffffffffu, s1, 1);
            s1 += __shfl_xor_sync(0xffffffffu, s1, 2);
            if ((lane & 3) == 0) {
                psum[wn * 64 + wm * 16 + (lane >> 2)]     = s0;
                psum[wn * 64 + wm * 16 + 8 + (lane >> 2)] = s1;
            }
        }

        // V(kt) must have arrived before phase 2 (pending: [V_t, K_{t+1}?])
        if (kt < t1) { asm volatile("cp.async.wait_group 1;"); }
        else         { asm volatile("cp.async.wait_group 0;"); }
        __syncthreads();

        if (tid < 64)
            l_run[tid] = l_run[tid] * rscale[tid] + psum[tid] + psum[64 + tid];

        // ---- Phase 2: O = O*scale + P V ----
#pragma unroll
        for (int mt = 0; mt < 2; ++mt) {
            float sL = rscale[wm2 * 32 + mt * 16 + (lane >> 2)];
            float sH = rscale[wm2 * 32 + mt * 16 + 8 + (lane >> 2)];
#pragma unroll
            for (int nt = 0; nt < 8; ++nt) {
                o_acc[mt][nt][0] *= sL; o_acc[mt][nt][1] *= sL;
                o_acc[mt][nt][2] *= sH; o_acc[mt][nt][3] *= sH;
            }
        }

#pragma unroll
        for (int ks2 = 0; ks2 < 4; ++ks2) {
            unsigned int aph[2][4], apl[2][4];
#pragma unroll
            for (int mt = 0; mt < 2; ++mt) {
                int row = wm2 * 32 + mt * 16 + (lane & 15);
                int col = ks2 * 16 + (lane >> 4) * 8;
                LDSM4(aph[mt], smem_u32(sm + ATT_PH + row * PSTR + col));
                LDSM4(apl[mt], smem_u32(sm + ATT_PL + row * PSTR + col));
            }
#pragma unroll
            for (int ng = 0; ng < 4; ++ng) {
                int vr = ks2 * 16 + ((lane >> 3) & 1) * 8 + (lane & 7);
                int vc = wn2 * 64 + ng * 16 + (lane >> 4) * 8;
                unsigned int bvh[4], bvl[4];
                LDSM4T(bvh, smem_u32(sm + ATT_VH + vr * DS + vc));
                LDSM4T(bvl, smem_u32(sm + ATT_VL + vr * DS + vc));
#pragma unroll
                for (int mt = 0; mt < 2; ++mt)
#pragma unroll
                    for (int o = 0; o < 4; o += 2) {
                        float* cc = o_acc[mt][ng * 2 + (o >> 1)];
                        MMA16816(cc, aph[mt], bvh[o], bvh[o + 1]);
                        MMA16816(cc, aph[mt], bvl[o], bvl[o + 1]);
                        MMA16816(cc, apl[mt], bvh[o], bvh[o + 1]);
                    }
            }
        }
        __syncthreads();          // all warps done with V tile + P

        if (kt < t1) {
            ISSUE_V(k0 + 64);
            asm volatile("cp.async.wait_group 1;");   // K(t+1) arrived
            __syncthreads();
        }
    }

    // Epilogue
#pragma unroll
    for (int mt = 0; mt < 2; ++mt) {
        int rL = wm2 * 32 + mt * 16 + (lane >> 2);
        int rH = rL + 8;
        float invL = 1.f / l_run[rL];
        float invH = 1.f / l_run[rH];
#pragma unroll
        for (int nt = 0; nt < 8; ++nt) {
            int col = wn2 * 64 + nt * 8 + (lane & 3) * 2;
            size_t gL = (size_t)(q0 + rL) * HIDN + h * HD + col;
            size_t gH = (size_t)(q0 + rH) * HIDN + h * HD + col;
            float v0 = o_acc[mt][nt][0] * invL, v1 = o_acc[mt][nt][1] * invL;
            float v2 = o_acc[mt][nt][2] * invH, v3 = o_acc[mt][nt][3] * invH;
            __nv_bfloat16 h0 = __float2bfloat16_rn(v0), h1 = __float2bfloat16_rn(v1);
            __nv_bfloat16 h2 = __float2bfloat16_rn(v2), h3 = __float2bfloat16_rn(v3);
            *(__nv_bfloat162*)(Oh + gL) = __halves2bfloat162(h0, h1);
            *(__nv_bfloat162*)(Oh + gH) = __halves2bfloat162(h2, h3);
            *(__nv_bfloat162*)(Ol + gL) = __halves2bfloat162(
                __float2bfloat16_rn(v0 - __bfloat162float(h0)),
                __float2bfloat16_rn(v1 - __bfloat162float(h1)));
            *(__nv_bfloat162*)(Ol + gH) = __halves2bfloat162(
                __float2bfloat16_rn(v2 - __bfloat162float(h2)),
                __float2bfloat16_rn(v3 - __bfloat162float(h3)));
        }
    }
#undef ISSUE_K
#undef ISSUE_V
}

// ---------------------------------------------------------------------------
extern "C" void kernel_launch(void* const* d_in, const int* in_sizes, int n_in,
                              void* d_out, int out_size)
{
    const float* hidden = (const float*)d_in[0];
    const float* cosv   = (const float*)d_in[1];
    const float* sinv   = (const float*)d_in[2];
    const float* q_w    = (const float*)d_in[3];
    const float* k_w    = (const float*)d_in[4];
    const float* v_w    = (const float*)d_in[5];
    const float* o_w    = (const float*)d_in[6];
    const float* q_nw   = (const float*)d_in[7];
    const float* k_nw   = (const float*)d_in[8];

    float* qkvp;
    cudaGetSymbolAddress((void**)&qkvp, g_qkv);

    __nv_bfloat16 *hid_h, *hid_l, *w_h, *w_l, *ow_h, *ow_l, *at_h, *at_l,
                  *q_h, *q_l, *k_h, *k_l, *v_h, *v_l;
    cudaGetSymbolAddress((void**)&hid_h, sb_hid_hi);
    cudaGetSymbolAddress((void**)&hid_l, sb_hid_lo);
    cudaGetSymbolAddress((void**)&w_h, sb_w_hi);
    cudaGetSymbolAddress((void**)&w_l, sb_w_lo);
    cudaGetSymbolAddress((void**)&ow_h, sb_ow_hi);
    cudaGetSymbolAddress((void**)&ow_l, sb_ow_lo);
    cudaGetSymbolAddress((void**)&at_h, sb_at_hi);
    cudaGetSymbolAddress((void**)&at_l, sb_at_lo);
    cudaGetSymbolAddress((void**)&q_h, sbq_hi);
    cudaGetSymbolAddress((void**)&q_l, sbq_lo);
    cudaGetSymbolAddress((void**)&k_h, sbk_hi);
    cudaGetSymbolAddress((void**)&k_l, sbk_lo);
    cudaGetSymbolAddress((void**)&v_h, sbv_hi);
    cudaGetSymbolAddress((void**)&v_l, sbv_lo);

    const int gemm_smem = 2 * 4 * GSTG * (int)sizeof(__nv_bfloat16);  // 81,920
    cudaFuncSetAttribute(gemm_bf16split, cudaFuncAttributeMaxDynamicSharedMemorySize,
                         gemm_smem);
    cudaFuncSetAttribute(attn_mma_kernel, cudaFuncAttributeMaxDynamicSharedMemorySize,
                         ATT_SMEM_BYTES);

    // Fused split: hidden, q_w, k_w, v_w (into one [q;k;v] buffer), o_w
    SplitSegs segs;
    long n_hid = (long)T_TOK * HIDN / 4;
    long n_qw  = (long)HIDN * HIDN / 4;
    long n_kw  = (long)NKV * HD * HIDN / 4;
    segs.src[0] = (const float4*)hidden; segs.hi[0] = (__nv_bfloat162*)hid_h;
    segs.lo[0] = (__nv_bfloat162*)hid_l; segs.end[0] = n_hid;
    segs.src[1] = (const float4*)q_w;    segs.hi[1] = (__nv_bfloat162*)w_h;
    segs.lo[1] = (__nv_bfloat162*)w_l;   segs.end[1] = segs.end[0] + n_qw;
    segs.src[2] = (const float4*)k_w;
    segs.hi[2] = (__nv_bfloat162*)(w_h + (size_t)HIDN * HIDN);
    segs.lo[2] = (__nv_bfloat162*)(w_l + (size_t)HIDN * HIDN);
    segs.end[2] = segs.end[1] + n_kw;
    segs.src[3] = (const float4*)v_w;
    segs.hi[3] = (__nv_bfloat162*)(w_h + (size_t)HIDN * HIDN + (size_t)NKV * HD * HIDN);
    segs.lo[3] = (__nv_bfloat162*)(w_l + (size_t)HIDN * HIDN + (size_t)NKV * HD * HIDN);
    segs.end[3] = segs.end[2] + n_kw;
    segs.src[4] = (const float4*)o_w;    segs.hi[4] = (__nv_bfloat162*)ow_h;
    segs.lo[4] = (__nv_bfloat162*)ow_l;  segs.end[4] = segs.end[3] + n_qw;
    long total_thr = segs.end[4] / 4;
    split_all_kernel<<<(unsigned)((total_thr + 255) / 256), 256>>>(segs);

    // Fused QKV projection: one N=4096 GEMM
    gemm_bf16split<<<dim3(4096 / 128, T_TOK / 128), 256, gemm_smem>>>(
        hid_h, hid_l, w_h, w_l, qkvp, T_TOK, 4096, HIDN);

    // RMSNorm + RoPE -> bf16 hi/lo
    norm_rope_kernel<<<T_TOK, 256>>>(cosv, sinv, q_nw, k_nw);

    // Attention (pipelined K/V loads)
    attn_mma_kernel<<<dim3(T_TOK / 64, NH), 256, ATT_SMEM_BYTES>>>(
        q_h, q_l, k_h, k_l, v_h, v_l, at_h, at_l);

    // Output projection
    gemm_bf16split<<<dim3(HIDN / 128, T_TOK / 128), 256, gemm_smem>>>(
        at_h, at_l, ow_h, ow_l, (float*)d_out, T_TOK, HIDN, HIDN);
}

// round 9
// speedup vs baseline: 2.5303x; 1.0022x over previous
#include <cuda_runtime.h>
#include <cuda_bf16.h>
#include <stdint.h>
#include <math.h>

// Problem constants
#define T_TOK 4096
#define HIDN  2048
#define NH    8
#define NKV   4
#define HD    256
#define SWIN  1024

// GEMM tiling (2-stage, 2 CTAs/SM)
#define GBK 32
#define GSTRIDE 40
#define GSTG (128 * GSTRIDE)

// Attention smem layout (bf16 element offsets)
#define DS   264
#define PSTR 72
#define ATT_QH 0
#define ATT_QL (64 * DS)
#define ATT_KH (2 * 64 * DS)
#define ATT_KL (3 * 64 * DS)
#define ATT_VH (4 * 64 * DS)
#define ATT_VL (5 * 64 * DS)
#define ATT_PH (6 * 64 * DS)
#define ATT_PL (ATT_PH + 64 * PSTR)
#define ATT_F  (ATT_PL + 64 * PSTR)
// float block: m_st[2][64] | l_st[2][64] | pmax[128] | psum[128] = 512 floats
#define ATT_SMEM_BYTES (ATT_F * 2 + 512 * 4)

// Scratch (static device globals — allocation-free)
__device__ float g_qkv[T_TOK * 4096];   // cols 0-2047 q, 2048-3071 k, 3072-4095 v

__device__ __nv_bfloat16 sb_hid_hi[T_TOK * HIDN], sb_hid_lo[T_TOK * HIDN];
__device__ __nv_bfloat16 sb_w_hi[4096 * HIDN],    sb_w_lo[4096 * HIDN];  // [q;k;v]
__device__ __nv_bfloat16 sb_ow_hi[HIDN * HIDN],   sb_ow_lo[HIDN * HIDN];
__device__ __nv_bfloat16 sb_at_hi[T_TOK * HIDN],  sb_at_lo[T_TOK * HIDN];

__device__ __nv_bfloat16 sbq_hi[T_TOK * HIDN],     sbq_lo[T_TOK * HIDN];
__device__ __nv_bfloat16 sbk_hi[T_TOK * NKV * HD], sbk_lo[T_TOK * NKV * HD];
__device__ __nv_bfloat16 sbv_hi[T_TOK * NKV * HD], sbv_lo[T_TOK * NKV * HD];

// ---------------------------------------------------------------------------
#define LDSM4(R, addr) \
    asm volatile("ldmatrix.sync.aligned.m8n8.x4.shared.b16 {%0,%1,%2,%3}, [%4];" \
                 : "=r"((R)[0]), "=r"((R)[1]), "=r"((R)[2]), "=r"((R)[3]) : "r"(addr))

#define LDSM4T(R, addr) \
    asm volatile("ldmatrix.sync.aligned.m8n8.x4.trans.shared.b16 {%0,%1,%2,%3}, [%4];" \
                 : "=r"((R)[0]), "=r"((R)[1]), "=r"((R)[2]), "=r"((R)[3]) : "r"(addr))

#define MMA16816(Cacc, A, b0, b1) \
    asm volatile("mma.sync.aligned.m16n8k16.row.col.f32.bf16.bf16.f32 " \
                 "{%0,%1,%2,%3}, {%4,%5,%6,%7}, {%8,%9}, {%0,%1,%2,%3};" \
                 : "+f"((Cacc)[0]), "+f"((Cacc)[1]), "+f"((Cacc)[2]), "+f"((Cacc)[3]) \
                 : "r"((A)[0]), "r"((A)[1]), "r"((A)[2]), "r"((A)[3]), "r"(b0), "r"(b1))

#define CPA16(dst, src) \
    asm volatile("cp.async.cg.shared.global [%0], [%1], 16;" :: "r"(dst), "l"(src))

__device__ __forceinline__ unsigned int smem_u32(const void* p) {
    return (unsigned int)__cvta_generic_to_shared(p);
}

// ---------------------------------------------------------------------------
// Fused split: all 5 tensors in one launch, 4 float4s per thread (MLP=4).
// ---------------------------------------------------------------------------
struct SplitSegs {
    const float4* src[5];
    __nv_bfloat162* hi[5];
    __nv_bfloat162* lo[5];
    long end[5];
};

__global__ __launch_bounds__(256) void split_all_kernel(SplitSegs segs)
{
    long base = ((long)blockIdx.x * blockDim.x + threadIdx.x) * 4;
    if (base >= segs.end[4]) return;
    int s = 0;
    while (base >= segs.end[s]) ++s;
    long start = (s == 0) ? 0 : segs.end[s - 1];
    long loc = base - start;
    const float4* src = segs.src[s] + loc;
    __nv_bfloat162* hi = segs.hi[s] + 2 * loc;
    __nv_bfloat162* lo = segs.lo[s] + 2 * loc;
#pragma unroll
    for (int j = 0; j < 4; ++j) {
        float4 v = src[j];
        __nv_bfloat16 h0 = __float2bfloat16_rn(v.x);
        __nv_bfloat16 h1 = __float2bfloat16_rn(v.y);
        __nv_bfloat16 h2 = __float2bfloat16_rn(v.z);
        __nv_bfloat16 h3 = __float2bfloat16_rn(v.w);
        hi[2 * j]     = __halves2bfloat162(h0, h1);
        hi[2 * j + 1] = __halves2bfloat162(h2, h3);
        lo[2 * j]     = __halves2bfloat162(
            __float2bfloat16_rn(v.x - __bfloat162float(h0)),
            __float2bfloat16_rn(v.y - __bfloat162float(h1)));
        lo[2 * j + 1] = __halves2bfloat162(
            __float2bfloat16_rn(v.z - __bfloat162float(h2)),
            __float2bfloat16_rn(v.w - __bfloat162float(h3)));
    }
}

// ---------------------------------------------------------------------------
// Split-bf16 tensor-core NT GEMM, 2-stage cp.async, 2 CTAs/SM (validated R7).
// ---------------------------------------------------------------------------
__global__ __launch_bounds__(256, 2) void gemm_bf16split(
    const __nv_bfloat16* __restrict__ Ah, const __nv_bfloat16* __restrict__ Al,
    const __nv_bfloat16* __restrict__ Bh, const __nv_bfloat16* __restrict__ Bl,
    float* __restrict__ C, int M, int N, int K)
{
    extern __shared__ __nv_bfloat16 sm[];
    const int tid = threadIdx.x;
    const int bm = blockIdx.y * 128, bn = blockIdx.x * 128;
    const int lane = tid & 31, wid = tid >> 5;
    const int wm = wid & 3, wn = wid >> 2;

#define GEMM_ISSUE(buf, k0)                                                        \
    {                                                                              \
        __nv_bfloat16* base = sm + (buf) * 4 * GSTG;                               \
        _Pragma("unroll")                                                          \
        for (int half = 0; half < 2; ++half) {                                     \
            int c = tid + half * 256;                                              \
            int row = c >> 2, cc = c & 3;                                          \
            unsigned int sA = smem_u32(base + row * GSTRIDE + cc * 8);             \
            const __nv_bfloat16* gAh = Ah + (size_t)(bm + row) * K + (k0) + cc*8;  \
            const __nv_bfloat16* gAl = Al + (size_t)(bm + row) * K + (k0) + cc*8;  \
            const __nv_bfloat16* gBh = Bh + (size_t)(bn + row) * K + (k0) + cc*8;  \
            const __nv_bfloat16* gBl = Bl + (size_t)(bn + row) * K + (k0) + cc*8;  \
            CPA16(sA, gAh);                                                        \
            CPA16(sA + GSTG * 2, gAl);                                             \
            CPA16(sA + GSTG * 4, gBh);                                             \
            CPA16(sA + GSTG * 6, gBl);                                             \
        }                                                                          \
        asm volatile("cp.async.commit_group;");                                    \
    }

    float acc[16][4];
#pragma unroll
    for (int t = 0; t < 16; ++t)
#pragma unroll
        for (int j = 0; j < 4; ++j) acc[t][j] = 0.f;

    GEMM_ISSUE(0, 0);

    const int iters = K / GBK;
    for (int it = 0; it < iters; ++it) {
        if (it + 1 < iters) {
            GEMM_ISSUE((it + 1) & 1, (it + 1) * GBK);
            asm volatile("cp.async.wait_group 1;");
        } else {
            asm volatile("cp.async.wait_group 0;");
        }
        __syncthreads();

        const __nv_bfloat16* st = sm + (it & 1) * 4 * GSTG;
#pragma unroll
        for (int ks = 0; ks < 2; ++ks) {
            unsigned int ah[2][4], al[2][4];
#pragma unroll
            for (int mt = 0; mt < 2; ++mt) {
                int row = wm * 32 + mt * 16 + (lane & 15);
                int col = ks * 16 + (lane >> 4) * 8;
                unsigned int ad = smem_u32(st + row * GSTRIDE + col);
                LDSM4(ah[mt], ad);
                LDSM4(al[mt], ad + GSTG * 2);
            }
#pragma unroll
            for (int p = 0; p < 4; ++p) {
                int r = lane & 7, g = lane >> 3;
                int nrow = wn * 64 + p * 16 + ((g >> 1) & 1) * 8 + r;
                int col = ks * 16 + (g & 1) * 8;
                unsigned int bd = smem_u32(st + 2 * GSTG + nrow * GSTRIDE + col);
                unsigned int bh[4], bl[4];
                LDSM4(bh, bd);
                LDSM4(bl, bd + GSTG * 2);
#pragma unroll
                for (int mt = 0; mt < 2; ++mt)
#pragma unroll
                    for (int o = 0; o < 4; o += 2) {
                        float* cc = acc[mt * 8 + p * 2 + (o >> 1)];
                        MMA16816(cc, ah[mt], bh[o], bh[o + 1]);
                        MMA16816(cc, ah[mt], bl[o], bl[o + 1]);
                        MMA16816(cc, al[mt], bh[o], bh[o + 1]);
                    }
            }
        }
        __syncthreads();
    }

#pragma unroll
    for (int mt = 0; mt < 2; ++mt)
#pragma unroll
        for (int nt = 0; nt < 8; ++nt) {
            float* cc = acc[mt * 8 + nt];
            int r = bm + wm * 32 + mt * 16 + (lane >> 2);
            int cl = bn + wn * 64 + nt * 8 + (lane & 3) * 2;
            *(float2*)&C[(size_t)r * N + cl]       = make_float2(cc[0], cc[1]);
            *(float2*)&C[(size_t)(r + 8) * N + cl] = make_float2(cc[2], cc[3]);
        }
#undef GEMM_ISSUE
}

// ---------------------------------------------------------------------------
// RMSNorm (+weight) + RoPE, warp-per-role (reads fused g_qkv).
// ---------------------------------------------------------------------------
__device__ __forceinline__ void store_hl4(__nv_bfloat16* dh, __nv_bfloat16* dl,
                                          size_t off, float4 v)
{
    __nv_bfloat16 h0 = __float2bfloat16_rn(v.x), h1 = __float2bfloat16_rn(v.y);
    __nv_bfloat16 h2 = __float2bfloat16_rn(v.z), h3 = __float2bfloat16_rn(v.w);
    union { __nv_bfloat162 b[2]; uint2 u; } ph, pl;
    ph.b[0] = __halves2bfloat162(h0, h1);
    ph.b[1] = __halves2bfloat162(h2, h3);
    pl.b[0] = __halves2bfloat162(__float2bfloat16_rn(v.x - __bfloat162float(h0)),
                                 __float2bfloat16_rn(v.y - __bfloat162float(h1)));
    pl.b[1] = __halves2bfloat162(__float2bfloat16_rn(v.z - __bfloat162float(h2)),
                                 __float2bfloat16_rn(v.w - __bfloat162float(h3)));
    *(uint2*)(dh + off) = ph.u;
    *(uint2*)(dl + off) = pl.u;
}

__global__ __launch_bounds__(256) void norm_rope_kernel(
    const float* __restrict__ cosv, const float* __restrict__ sinv,
    const float* __restrict__ q_nw, const float* __restrict__ k_nw)
{
    const int t = blockIdx.x;
    const int wid = threadIdx.x >> 5, lane = threadIdx.x & 31;
    const int cA = lane * 4, cB = 128 + lane * 4;

#pragma unroll
    for (int rr = 0; rr < 2; ++rr) {
        const int role = wid * 2 + rr;
        const float* src;
        const float* w = nullptr;
        bool rope = true;
        __nv_bfloat16 *dh, *dl;
        size_t doff;
        if (role < 8) {
            src = g_qkv + (size_t)t * 4096 + role * HD; w = q_nw;
            dh = sbq_hi; dl = sbq_lo; doff = (size_t)t * HIDN + role * HD;
        } else if (role < 12) {
            src = g_qkv + (size_t)t * 4096 + 2048 + (role - 8) * HD; w = k_nw;
            dh = sbk_hi; dl = sbk_lo; doff = (size_t)t * 1024 + (role - 8) * HD;
        } else {
            src = g_qkv + (size_t)t * 4096 + 3072 + (role - 12) * HD; rope = false;
            dh = sbv_hi; dl = sbv_lo; doff = (size_t)t * 1024 + (role - 12) * HD;
        }

        float4 a = *(const float4*)(src + cA);
        float4 b = *(const float4*)(src + cB);
        float ss = a.x*a.x + a.y*a.y + a.z*a.z + a.w*a.w
                 + b.x*b.x + b.y*b.y + b.z*b.z + b.w*b.w;
#pragma unroll
        for (int o = 16; o >= 1; o >>= 1) ss += __shfl_xor_sync(0xffffffffu, ss, o);
        float rn = rsqrtf(ss * (1.f / HD) + 1e-6f);

        float4 ya, yb;
        if (w) {
            float4 wa = *(const float4*)(w + cA);
            float4 wb = *(const float4*)(w + cB);
            ya = make_float4(a.x*rn*wa.x, a.y*rn*wa.y, a.z*rn*wa.z, a.w*rn*wa.w);
            yb = make_float4(b.x*rn*wb.x, b.y*rn*wb.y, b.z*rn*wb.z, b.w*rn*wb.w);
        } else {
            ya = make_float4(a.x*rn, a.y*rn, a.z*rn, a.w*rn);
            yb = make_float4(b.x*rn, b.y*rn, b.z*rn, b.w*rn);
        }

        float4 oa = ya, ob = yb;
        if (rope) {
            const float* cp = cosv + (size_t)t * HD;
            const float* sp = sinv + (size_t)t * HD;
            float4 ca = *(const float4*)(cp + cA), cb = *(const float4*)(cp + cB);
            float4 sa = *(const float4*)(sp + cA), sb = *(const float4*)(sp + cB);
            oa = make_float4(ya.x*ca.x - yb.x*sa.x, ya.y*ca.y - yb.y*sa.y,
                             ya.z*ca.z - yb.z*sa.z, ya.w*ca.w - yb.w*sa.w);
            ob = make_float4(yb.x*cb.x + ya.x*sb.x, yb.y*cb.y + ya.y*sb.y,
                             yb.z*cb.z + ya.z*sb.z, yb.w*cb.w + ya.w*sb.w);
        }
        store_hl4(dh, dl, doff + cA, oa);
        store_hl4(dh, dl, doff + cB, ob);
    }
}

// ---------------------------------------------------------------------------
// Sliding-window flash attention: pipelined K/V loads + ping-pong softmax
// stats (no serial sections, 4 barriers/tile).
// ---------------------------------------------------------------------------
__global__ __launch_bounds__(256) void attn_mma_kernel(
    const __nv_bfloat16* __restrict__ Qh, const __nv_bfloat16* __restrict__ Ql,
    const __nv_bfloat16* __restrict__ Kh, const __nv_bfloat16* __restrict__ Kl,
    const __nv_bfloat16* __restrict__ Vh, const __nv_bfloat16* __restrict__ Vl,
    __nv_bfloat16* __restrict__ Oh, __nv_bfloat16* __restrict__ Ol)
{
    extern __shared__ __nv_bfloat16 sm[];
    float* fb   = (float*)(sm + ATT_F);
    // fb[0..127]: m_st[2][64]; fb[128..255]: l_st[2][64];
    // fb[256..383]: pmax[2][64]; fb[384..511]: psum[2][64]
    float* pmax = fb + 256;
    float* psum = fb + 384;

    const int qb = blockIdx.x, h = blockIdx.y;
    const int q0 = qb * 64;
    const int kvh = h >> 1;
    const int tid = threadIdx.x;
    const int lane = tid & 31, wid = tid >> 5;
    const int wm = wid & 3, wn = wid >> 2;
    const int wm2 = wid & 1, wn2 = wid >> 1;

    if (tid < 64) { fb[tid] = -1e30f; fb[128 + tid] = 0.f; }

#define ISSUE_K(k0)                                                            \
    {                                                                          \
        for (int i = tid; i < 2048; i += 256) {                                \
            int r = i >> 5, c = (i & 31) * 8;                                  \
            size_t g = (size_t)((k0) + r) * (NKV * HD) + kvh * HD + c;         \
            CPA16(smem_u32(sm + ATT_KH + r * DS + c), Kh + g);                 \
            CPA16(smem_u32(sm + ATT_KL + r * DS + c), Kl + g);                 \
        }                                                                      \
        asm volatile("cp.async.commit_group;");                                \
    }
#define ISSUE_V(k0)                                                            \
    {                                                                          \
        for (int i = tid; i < 2048; i += 256) {                                \
            int r = i >> 5, c = (i & 31) * 8;                                  \
            size_t g = (size_t)((k0) + r) * (NKV * HD) + kvh * HD + c;         \
            CPA16(smem_u32(sm + ATT_VH + r * DS + c), Vh + g);                 \
            CPA16(smem_u32(sm + ATT_VL + r * DS + c), Vl + g);                 \
        }                                                                      \
        asm volatile("cp.async.commit_group;");                                \
    }

    // Prologue: Q, K(t0), V(t0)
    for (int i = tid; i < 2048; i += 256) {
        int r = i >> 5, c = (i & 31) * 8;
        size_t g = (size_t)(q0 + r) * HIDN + h * HD + c;
        CPA16(smem_u32(sm + ATT_QH + r * DS + c), Qh + g);
        CPA16(smem_u32(sm + ATT_QL + r * DS + c), Ql + g);
    }
    asm volatile("cp.async.commit_group;");

    float o_acc[2][8][4];
#pragma unroll
    for (int mt = 0; mt < 2; ++mt)
#pragma unroll
        for (int nt = 0; nt < 8; ++nt)
#pragma unroll
            for (int e = 0; e < 4; ++e) o_acc[mt][nt][e] = 0.f;

    int jmin = q0 - (SWIN - 1); if (jmin < 0) jmin = 0;
    const int t0 = jmin >> 6;
    const int t1 = (q0 + 63) >> 6;
    const int ntiles = t1 - t0 + 1;

    ISSUE_K(t0 * 64);
    ISSUE_V(t0 * 64);
    asm volatile("cp.async.wait_group 1;");   // Q + K0 done (V0 may pend)
    __syncthreads();

    for (int kt = t0; kt <= t1; ++kt) {
        const int k0 = kt * 64;
        const int pp = (kt - t0) & 1;
        float* m_old = fb + pp * 64;
        float* m_newp = fb + (pp ^ 1) * 64;
        float* l_old = fb + 128 + pp * 64;
        float* l_newp = fb + 128 + (pp ^ 1) * 64;

        // ---- Phase 1: S = Q K^T ----
        float sacc[4][4];
#pragma unroll
        for (int nt = 0; nt < 4; ++nt)
#pragma unroll
            for (int e = 0; e < 4; ++e) sacc[nt][e] = 0.f;

#pragma unroll 4
        for (int ks = 0; ks < 16; ++ks) {
            unsigned int ah[4], al[4];
            {
                int row = wm * 16 + (lane & 15);
                int col = ks * 16 + (lane >> 4) * 8;
                LDSM4(ah, smem_u32(sm + ATT_QH + row * DS + col));
                LDSM4(al, smem_u32(sm + ATT_QL + row * DS + col));
            }
#pragma unroll
            for (int p = 0; p < 2; ++p) {
                int nrow = wn * 32 + p * 16 + ((lane >> 4) << 3) + (lane & 7);
                int col = ks * 16 + ((lane >> 3) & 1) * 8;
                unsigned int bh[4], bl[4];
                LDSM4(bh, smem_u32(sm + ATT_KH + nrow * DS + col));
                LDSM4(bl, smem_u32(sm + ATT_KL + nrow * DS + col));
#pragma unroll
                for (int o = 0; o < 4; o += 2) {
                    float* cc = sacc[p * 2 + (o >> 1)];
                    MMA16816(cc, ah, bh[o], bh[o + 1]);
                    MMA16816(cc, ah, bl[o], bl[o + 1]);
                    MMA16816(cc, al, bh[o], bh[o + 1]);
                }
            }
        }

        // Mask
        const int r_lo = q0 + wm * 16 + (lane >> 2);
        const int r_hi = r_lo + 8;
#pragma unroll
        for (int nt = 0; nt < 4; ++nt) {
#pragma unroll
            for (int e = 0; e < 2; ++e) {
                int j = k0 + wn * 32 + nt * 8 + (lane & 3) * 2 + e;
                if (!(j <= r_lo && r_lo - j < SWIN)) sacc[nt][e] = -1e30f;
                if (!(j <= r_hi && r_hi - j < SWIN)) sacc[nt][e + 2] = -1e30f;
            }
        }

        float mx0 = -1e30f, mx1 = -1e30f;
#pragma unroll
        for (int nt = 0; nt < 4; ++nt) {
            mx0 = fmaxf(mx0, fmaxf(sacc[nt][0], sacc[nt][1]));
            mx1 = fmaxf(mx1, fmaxf(sacc[nt][2], sacc[nt][3]));
        }
        mx0 = fmaxf(mx0, __shfl_xor_sync(0xffffffffu, mx0, 1));
        mx0 = fmaxf(mx0, __shfl_xor_sync(0xffffffffu, mx0, 2));
        mx1 = fmaxf(mx1, __shfl_xor_sync(0xffffffffu, mx1, 1));
        mx1 = fmaxf(mx1, __shfl_xor_sync(0xffffffffu, mx1, 2));
        if ((lane & 3) == 0) {
            pmax[wn * 64 + wm * 16 + (lane >> 2)]     = mx0;
            pmax[wn * 64 + wm * 16 + 8 + (lane >> 2)] = mx1;
        }
        __syncthreads();                            // (a) K consumed, pmax ready

        if (kt < t1) ISSUE_K(k0 + 64);              // prefetch next K

        // Stats: every thread computes what it needs locally (no serial section)
        float mo_t = 0.f, mn_t = 0.f;
        if (tid < 64) {
            mo_t = m_old[tid];
            mn_t = fmaxf(mo_t, fmaxf(pmax[tid], pmax[64 + tid]));
            m_newp[tid] = mn_t;
        }
        {
            const int pr0 = wm * 16 + (lane >> 2);
            const int pr1 = pr0 + 8;
            float m0v = fmaxf(m_old[pr0], fmaxf(pmax[pr0], pmax[64 + pr0]));
            float m1v = fmaxf(m_old[pr1], fmaxf(pmax[pr1], pmax[64 + pr1]));
            float s0 = 0.f, s1 = 0.f;
#pragma unroll
            for (int nt = 0; nt < 4; ++nt) {
                float p00 = (sacc[nt][0] > -1e29f) ? __expf(sacc[nt][0] - m0v) : 0.f;
                float p01 = (sacc[nt][1] > -1e29f) ? __expf(sacc[nt][1] - m0v) : 0.f;
                float p10 = (sacc[nt][2] > -1e29f) ? __expf(sacc[nt][2] - m1v) : 0.f;
                float p11 = (sacc[nt][3] > -1e29f) ? __expf(sacc[nt][3] - m1v) : 0.f;
                s0 += p00 + p01; s1 += p10 + p11;
                int colb = wn * 32 + nt * 8 + (lane & 3) * 2;
                __nv_bfloat16 h00 = __float2bfloat16_rn(p00);
                __nv_bfloat16 h01 = __float2bfloat16_rn(p01);
                __nv_bfloat16 h10 = __float2bfloat16_rn(p10);
                __nv_bfloat16 h11 = __float2bfloat16_rn(p11);
                *(__nv_bfloat162*)(sm + ATT_PH + pr0 * PSTR + colb) =
                    __halves2bfloat162(h00, h01);
                *(__nv_bfloat162*)(sm + ATT_PH + pr1 * PSTR + colb) =
                    __halves2bfloat162(h10, h11);
                *(__nv_bfloat162*)(sm + ATT_PL + pr0 * PSTR + colb) =
                    __halves2bfloat162(
                        __float2bfloat16_rn(p00 - __bfloat162float(h00)),
                        __float2bfloat16_rn(p01 - __bfloat162float(h01)));
                *(__nv_bfloat162*)(sm + ATT_PL + pr1 * PSTR + colb) =
                    __halves2bfloat162(
                        __float2bfloat16_rn(p10 - __bfloat162float(h10)),
                        __float2bfloat16_rn(p11 - __bfloat162float(h11)));
            }
            s0 += __shfl_xor_sync(0xffffffffu, s0, 1);
            s0 += __shfl_xor_sync(0xffffffffu, s0, 2);
            s1 += __shfl_xor_sync(0xffffffffu, s1, 1);
            s1 += __shfl_xor_sync(0xffffffffu, s1, 2);
            if ((lane & 3) == 0) {
                psum[wn * 64 + wm * 16 + (lane >> 2)]     = s0;
                psum[wn * 64 + wm * 16 + 8 + (lane >> 2)] = s1;
            }
        }

        // Rescale O while V(t) finishes loading (local rescale, phase-2 rows)
#pragma unroll
        for (int mt = 0; mt < 2; ++mt) {
            int r0 = wm2 * 32 + mt * 16 + (lane >> 2);
            int r1 = r0 + 8;
            float a0 = m_old[r0];
            float sL = __expf(a0 - fmaxf(a0, fmaxf(pmax[r0], pmax[64 + r0])));
            float a1 = m_old[r1];
            float sH = __expf(a1 - fmaxf(a1, fmaxf(pmax[r1], pmax[64 + r1])));
#pragma unroll
            for (int nt = 0; nt < 8; ++nt) {
                o_acc[mt][nt][0] *= sL; o_acc[mt][nt][1] *= sL;
                o_acc[mt][nt][2] *= sH; o_acc[mt][nt][3] *= sH;
            }
        }

        // V(kt) must have arrived (pending: [V_t, K_{t+1}?]); also P/psum ready
        if (kt < t1) { asm volatile("cp.async.wait_group 1;"); }
        else         { asm volatile("cp.async.wait_group 0;"); }
        __syncthreads();                            // (b)

        if (tid < 64)
            l_newp[tid] = l_old[tid] * __expf(mo_t - mn_t)
                          + psum[tid] + psum[64 + tid];

        // ---- Phase 2: O += P V ----
#pragma unroll
        for (int ks2 = 0; ks2 < 4; ++ks2) {
            unsigned int aph[2][4], apl[2][4];
#pragma unroll
            for (int mt = 0; mt < 2; ++mt) {
                int row = wm2 * 32 + mt * 16 + (lane & 15);
                int col = ks2 * 16 + (lane >> 4) * 8;
                LDSM4(aph[mt], smem_u32(sm + ATT_PH + row * PSTR + col));
                LDSM4(apl[mt], smem_u32(sm + ATT_PL + row * PSTR + col));
            }
#pragma unroll
            for (int ng = 0; ng < 4; ++ng) {
                int vr = ks2 * 16 + ((lane >> 3) & 1) * 8 + (lane & 7);
                int vc = wn2 * 64 + ng * 16 + (lane >> 4) * 8;
                unsigned int bvh[4], bvl[4];
                LDSM4T(bvh, smem_u32(sm + ATT_VH + vr * DS + vc));
                LDSM4T(bvl, smem_u32(sm + ATT_VL + vr * DS + vc));
#pragma unroll
                for (int mt = 0; mt < 2; ++mt)
#pragma unroll
                    for (int o = 0; o < 4; o += 2) {
                        float* cc = o_acc[mt][ng * 2 + (o >> 1)];
                        MMA16816(cc, aph[mt], bvh[o], bvh[o + 1]);
                        MMA16816(cc, aph[mt], bvl[o], bvl[o + 1]);
                        MMA16816(cc, apl[mt], bvh[o], bvh[o + 1]);
                    }
            }
        }
        __syncthreads();                            // (c) V + P consumed

        if (kt < t1) {
            ISSUE_V(k0 + 64);
            asm volatile("cp.async.wait_group 1;"); // K(t+1) arrived
            __syncthreads();                        // (d)
        }
    }

    // Epilogue
    float* l_fin = fb + 128 + (ntiles & 1) * 64;
#pragma unroll
    for (int mt = 0; mt < 2; ++mt) {
        int rL = wm2 * 32 + mt * 16 + (lane >> 2);
        int rH = rL + 8;
        float invL = 1.f / l_fin[rL];
        float invH = 1.f / l_fin[rH];
#pragma unroll
        for (int nt = 0; nt < 8; ++nt) {
            int col = wn2 * 64 + nt * 8 + (lane & 3) * 2;
            size_t gL = (size_t)(q0 + rL) * HIDN + h * HD + col;
            size_t gH = (size_t)(q0 + rH) * HIDN + h * HD + col;
            float v0 = o_acc[mt][nt][0] * invL, v1 = o_acc[mt][nt][1] * invL;
            float v2 = o_acc[mt][nt][2] * invH, v3 = o_acc[mt][nt][3] * invH;
            __nv_bfloat16 h0 = __float2bfloat16_rn(v0), h1 = __float2bfloat16_rn(v1);
            __nv_bfloat16 h2 = __float2bfloat16_rn(v2), h3 = __float2bfloat16_rn(v3);
            *(__nv_bfloat162*)(Oh + gL) = __halves2bfloat162(h0, h1);
            *(__nv_bfloat162*)(Oh + gH) = __halves2bfloat162(h2, h3);
            *(__nv_bfloat162*)(Ol + gL) = __halves2bfloat162(
                __float2bfloat16_rn(v0 - __bfloat162float(h0)),
                __float2bfloat16_rn(v1 - __bfloat162float(h1)));
            *(__nv_bfloat162*)(Ol + gH) = __halves2bfloat162(
                __float2bfloat16_rn(v2 - __bfloat162float(h2)),
                __float2bfloat16_rn(v3 - __bfloat162float(h3)));
        }
    }
#undef ISSUE_K
#undef ISSUE_V
}

// ---------------------------------------------------------------------------
extern "C" void kernel_launch(void* const* d_in, const int* in_sizes, int n_in,
                              void* d_out, int out_size)
{
    const float* hidden = (const float*)d_in[0];
    const float* cosv   = (const float*)d_in[1];
    const float* sinv   = (const float*)d_in[2];
    const float* q_w    = (const float*)d_in[3];
    const float* k_w    = (const float*)d_in[4];
    const float* v_w    = (const float*)d_in[5];
    const float* o_w    = (const float*)d_in[6];
    const float* q_nw   = (const float*)d_in[7];
    const float* k_nw   = (const float*)d_in[8];

    float* qkvp;
    cudaGetSymbolAddress((void**)&qkvp, g_qkv);

    __nv_bfloat16 *hid_h, *hid_l, *w_h, *w_l, *ow_h, *ow_l, *at_h, *at_l,
                  *q_h, *q_l, *k_h, *k_l, *v_h, *v_l;
    cudaGetSymbolAddress((void**)&hid_h, sb_hid_hi);
    cudaGetSymbolAddress((void**)&hid_l, sb_hid_lo);
    cudaGetSymbolAddress((void**)&w_h, sb_w_hi);
    cudaGetSymbolAddress((void**)&w_l, sb_w_lo);
    cudaGetSymbolAddress((void**)&ow_h, sb_ow_hi);
    cudaGetSymbolAddress((void**)&ow_l, sb_ow_lo);
    cudaGetSymbolAddress((void**)&at_h, sb_at_hi);
    cudaGetSymbolAddress((void**)&at_l, sb_at_lo);
    cudaGetSymbolAddress((void**)&q_h, sbq_hi);
    cudaGetSymbolAddress((void**)&q_l, sbq_lo);
    cudaGetSymbolAddress((void**)&k_h, sbk_hi);
    cudaGetSymbolAddress((void**)&k_l, sbk_lo);
    cudaGetSymbolAddress((void**)&v_h, sbv_hi);
    cudaGetSymbolAddress((void**)&v_l, sbv_lo);

    const int gemm_smem = 2 * 4 * GSTG * (int)sizeof(__nv_bfloat16);  // 81,920
    cudaFuncSetAttribute(gemm_bf16split, cudaFuncAttributeMaxDynamicSharedMemorySize,
                         gemm_smem);
    cudaFuncSetAttribute(attn_mma_kernel, cudaFuncAttributeMaxDynamicSharedMemorySize,
                         ATT_SMEM_BYTES);

    // Fused split: hidden, q_w, k_w, v_w (into one [q;k;v] buffer), o_w
    SplitSegs segs;
    long n_hid = (long)T_TOK * HIDN / 4;
    long n_qw  = (long)HIDN * HIDN / 4;
    long n_kw  = (long)NKV * HD * HIDN / 4;
    segs.src[0] = (const float4*)hidden; segs.hi[0] = (__nv_bfloat162*)hid_h;
    segs.lo[0] = (__nv_bfloat162*)hid_l; segs.end[0] = n_hid;
    segs.src[1] = (const float4*)q_w;    segs.hi[1] = (__nv_bfloat162*)w_h;
    segs.lo[1] = (__nv_bfloat162*)w_l;   segs.end[1] = segs.end[0] + n_qw;
    segs.src[2] = (const float4*)k_w;
    segs.hi[2] = (__nv_bfloat162*)(w_h + (size_t)HIDN * HIDN);
    segs.lo[2] = (__nv_bfloat162*)(w_l + (size_t)HIDN * HIDN);
    segs.end[2] = segs.end[1] + n_kw;
    segs.src[3] = (const float4*)v_w;
    segs.hi[3] = (__nv_bfloat162*)(w_h + (size_t)HIDN * HIDN + (size_t)NKV * HD * HIDN);
    segs.lo[3] = (__nv_bfloat162*)(w_l + (size_t)HIDN * HIDN + (size_t)NKV * HD * HIDN);
    segs.end[3] = segs.end[2] + n_kw;
    segs.src[4] = (const float4*)o_w;    segs.hi[4] = (__nv_bfloat162*)ow_h;
    segs.lo[4] = (__nv_bfloat162*)ow_l;  segs.end[4] = segs.end[3] + n_qw;
    long total_thr = segs.end[4] / 4;
    split_all_kernel<<<(unsigned)((total_thr + 255) / 256), 256>>>(segs);

    // Fused QKV projection: one N=4096 GEMM
    gemm_bf16split<<<dim3(4096 / 128, T_TOK / 128), 256, gemm_smem>>>(
        hid_h, hid_l, w_h, w_l, qkvp, T_TOK, 4096, HIDN);

    // RMSNorm + RoPE -> bf16 hi/lo
    norm_rope_kernel<<<T_TOK, 256>>>(cosv, sinv, q_nw, k_nw);

    // Attention (pipelined K/V loads, ping-pong stats)
    attn_mma_kernel<<<dim3(T_TOK / 64, NH), 256, ATT_SMEM_BYTES>>>(
        q_h, q_l, k_h, k_l, v_h, v_l, at_h, at_l);

    // Output projection
    gemm_bf16split<<<dim3(HIDN / 128, T_TOK / 128), 256, gemm_smem>>>(
        at_h, at_l, ow_h, ow_l, (float*)d_out, T_TOK, HIDN, HIDN);
}